// round 1
// baseline (speedup 1.0000x reference)
#include <cuda_runtime.h>
#include <math.h>

#define LSEQ   2048
#define DMODEL 2048
#define NH     16
#define DKTOT  1024
#define HDKc   64
#define HDVc   128

// Scratch: one big __device__ array (no allocation allowed).
// Layout (float offsets):
//  0      xc   (4M)     conv output (L,D)
//  4M     qb   (2M)     q = silu(xc@Wq)   (L,1024)
//  6M     kb   (2M)     k                 (L,1024)
//  8M     vb   (4M)     v                 (L,2048)
//  12M    gb   (4M)     g                 (L,2048)
//  16M    qr   (2M)     rotary(q)*scale   (L,1024)
//  18M    kr   (2M)     rotary(k)         (L,1024)
//  20M    oa   (4M)     attention out     (L,2048)
//  24M    oc   (4M)     ln*silu(g)        (L,2048)
//  28M    slot (32768 ints), score (+32768), qscale (+65536)
__device__ float g_scratch[(29u << 20)];

__device__ __forceinline__ float silu_f(float x) { return x / (1.f + expf(-x)); }

// ---------------- conv + silu ----------------
__global__ void conv_kernel(const float* __restrict__ x, const float* __restrict__ cw,
                            float* __restrict__ xc)
{
    int idx = blockIdx.x * blockDim.x + threadIdx.x;   // 0 .. L*D-1
    int l = idx >> 11;
    int d = idx & (DMODEL - 1);
    float xp = (l > 0) ? x[idx - DMODEL] : 0.f;
    float v  = xp * cw[2 * d] + x[idx] * cw[2 * d + 1];
    xc[idx] = silu_f(v);
}

// ---------------- SGEMM: C = [silu](A @ B), A: Mx K row-major, B: K x N ----------------
template <bool SILU>
__global__ void __launch_bounds__(256) sgemm_kernel(
    const float* __restrict__ A, const float* __restrict__ B,
    float* __restrict__ C, int N, int K)
{
    __shared__ float As[8][128];   // [k][m] transposed
    __shared__ float Bs[8][128];   // [k][n]
    const int tid = threadIdx.x;
    const int bx = blockIdx.x, by = blockIdx.y;
    const int tx = tid & 15, ty = tid >> 4;
    const int aRow = tid >> 1, aCol = (tid & 1) << 2;
    const int bRow = tid >> 5, bCol = (tid & 31) << 2;
    const float* Ap = A + (size_t)(by * 128 + aRow) * K + aCol;
    const float* Bp = B + (size_t)bRow * N + bx * 128 + bCol;

    float acc[8][8];
    #pragma unroll
    for (int i = 0; i < 8; i++)
        #pragma unroll
        for (int j = 0; j < 8; j++) acc[i][j] = 0.f;

    for (int k0 = 0; k0 < K; k0 += 8) {
        float4 a4 = *(const float4*)(Ap + k0);
        float4 b4 = *(const float4*)(Bp + (size_t)k0 * N);
        As[aCol + 0][aRow] = a4.x; As[aCol + 1][aRow] = a4.y;
        As[aCol + 2][aRow] = a4.z; As[aCol + 3][aRow] = a4.w;
        *(float4*)&Bs[bRow][bCol] = b4;
        __syncthreads();
        #pragma unroll
        for (int kk = 0; kk < 8; kk++) {
            float ar[8], br[8];
            *(float4*)(ar)     = *(const float4*)&As[kk][ty * 8];
            *(float4*)(ar + 4) = *(const float4*)&As[kk][ty * 8 + 4];
            *(float4*)(br)     = *(const float4*)&Bs[kk][tx * 4];        // cols tx*4..+3
            *(float4*)(br + 4) = *(const float4*)&Bs[kk][64 + tx * 4];   // cols 64+tx*4..+3
            #pragma unroll
            for (int i = 0; i < 8; i++)
                #pragma unroll
                for (int j = 0; j < 8; j++)
                    acc[i][j] += ar[i] * br[j];
        }
        __syncthreads();
    }
    #pragma unroll
    for (int i = 0; i < 8; i++) {
        size_t row = (size_t)(by * 128 + ty * 8 + i);
        float4 o0, o1;
        if (SILU) {
            o0 = make_float4(silu_f(acc[i][0]), silu_f(acc[i][1]), silu_f(acc[i][2]), silu_f(acc[i][3]));
            o1 = make_float4(silu_f(acc[i][4]), silu_f(acc[i][5]), silu_f(acc[i][6]), silu_f(acc[i][7]));
        } else {
            o0 = make_float4(acc[i][0], acc[i][1], acc[i][2], acc[i][3]);
            o1 = make_float4(acc[i][4], acc[i][5], acc[i][6], acc[i][7]);
        }
        *(float4*)(C + row * N + bx * 128 + tx * 4)      = o0;
        *(float4*)(C + row * N + bx * 128 + 64 + tx * 4) = o1;
    }
}

// ---------------- router: logits = v_head @ router_w, 2-way softmax argmax ----------------
__global__ void router_kernel(const float* __restrict__ v, const float* __restrict__ rw,
                              int* __restrict__ slot, float* __restrict__ score)
{
    int w = (blockIdx.x * blockDim.x + threadIdx.x) >> 5;   // 0 .. L*NH-1
    int lane = threadIdx.x & 31;
    int l = w >> 4, h = w & 15;
    const float* vp = v + (size_t)l * DMODEL + h * HDVc;
    float4 vv = *(const float4*)(vp + lane * 4);
    const float* rp = rw + h * HDVc * 2 + lane * 8;   // rw[h][d][r], d = lane*4..+3
    float4 r0 = *(const float4*)(rp);
    float4 r1 = *(const float4*)(rp + 4);
    float l0 = vv.x * r0.x + vv.y * r0.z + vv.z * r1.x + vv.w * r1.z;
    float l1 = vv.x * r0.y + vv.y * r0.w + vv.z * r1.y + vv.w * r1.w;
    #pragma unroll
    for (int off = 16; off; off >>= 1) {
        l0 += __shfl_xor_sync(0xffffffffu, l0, off);
        l1 += __shfl_xor_sync(0xffffffffu, l1, off);
    }
    if (lane == 0) {
        int s = (l1 > l0) ? 1 : 0;                       // argmax (ties -> 0, like jnp)
        slot[l * NH + h]  = s;
        score[l * NH + h] = 1.f / (1.f + expf(-fabsf(l0 - l1)));  // softmax prob of winner
    }
}

// ---------------- per-head serial scan: norm = 1/count(slot so far); qscale = score*norm/8 ----------------
__global__ void scan_kernel(const int* __restrict__ slot, const float* __restrict__ score,
                            float* __restrict__ qscale)
{
    __shared__ int   sl[LSEQ];
    __shared__ float nm[LSEQ];
    int h = blockIdx.x;
    for (int i = threadIdx.x; i < LSEQ; i += blockDim.x) sl[i] = slot[i * NH + h];
    __syncthreads();
    if (threadIdx.x == 0) {
        int c0 = 0, c1 = 0;
        for (int i = 0; i < LSEQ; i++) {
            int c = sl[i] ? ++c1 : ++c0;
            nm[i] = 1.f / (float)c;
        }
    }
    __syncthreads();
    for (int i = threadIdx.x; i < LSEQ; i += blockDim.x)
        qscale[i * NH + h] = score[i * NH + h] * nm[i] * 0.125f;   // fold HDK^-0.5 = 1/8
}

// ---------------- rotary (+ fold qscale into q) ----------------
__global__ void rotary_kernel(const float* __restrict__ q, const float* __restrict__ k,
                              const float* __restrict__ qscale,
                              float* __restrict__ qr, float* __restrict__ kr)
{
    __shared__ float cs[32], sn[32];
    int l = blockIdx.x;
    if (threadIdx.x < 32) {
        // inv_freq[i] = 10000^(-i/32)
        float invf = expf(-(float)threadIdx.x * (logf(10000.f) / 32.f));
        float f = (float)l * invf;
        sincosf(f, &sn[threadIdx.x], &cs[threadIdx.x]);
    }
    __syncthreads();
    for (int it = threadIdx.x; it < 2 * DKTOT; it += blockDim.x) {
        int isK = it >> 10;
        int idx = it & 1023;
        int h = idx >> 6, d = idx & 63;
        const float* src = isK ? k : q;
        size_t base = (size_t)l * DKTOT + h * HDKc;
        float val;
        if (d < 32) val = src[base + d] * cs[d]      - src[base + d + 32] * sn[d];
        else        val = src[base + d] * cs[d - 32] + src[base + d - 32] * sn[d - 32];
        if (isK) kr[base + d] = val;
        else     qr[base + d] = val * qscale[l * NH + h];
    }
}

// ---------------- gated causal attention: o = (tril(qr@kr^T with slot gate)) @ v ----------------
__global__ void __launch_bounds__(256) attn_kernel(
    const float* __restrict__ qr, const float* __restrict__ kr,
    const float* __restrict__ v, const int* __restrict__ slot,
    float* __restrict__ oa)
{
    __shared__ float Qs[64][64];    // [k-dim][row]   16 KB
    __shared__ float Ks[64][32];    // [k-dim][col]    8 KB
    __shared__ float Vs[32][128];   // [kv][c]        16 KB
    __shared__ float Ss[32][64];    // [j][i] (XOR-swizzled i-groups)  8 KB -> 48 KB total
    const int it  = 31 - blockIdx.x;     // heavy row-tiles scheduled first
    const int h   = blockIdx.y;
    const int tid = threadIdx.x;
    const int tx = tid & 15, ty = tid >> 4;
    const int row0 = it * 64;

    #pragma unroll
    for (int rep = 0; rep < 4; rep++) {
        int idx = rep * 256 + tid;
        int r = idx >> 4;
        int d4 = (idx & 15) << 2;
        float4 a = *(const float4*)(qr + (size_t)(row0 + r) * DKTOT + h * HDKc + d4);
        Qs[d4 + 0][r] = a.x; Qs[d4 + 1][r] = a.y; Qs[d4 + 2][r] = a.z; Qs[d4 + 3][r] = a.w;
    }
    int si[4], gi[4];
    #pragma unroll
    for (int i = 0; i < 4; i++) { gi[i] = row0 + ty * 4 + i; si[i] = slot[gi[i] * NH + h]; }

    float acc[4][8];
    #pragma unroll
    for (int i = 0; i < 4; i++)
        #pragma unroll
        for (int j = 0; j < 8; j++) acc[i][j] = 0.f;

    const int njt = 2 * it + 2;
    for (int jt = 0; jt < njt; jt++) {
        const int col0 = jt * 32;
        __syncthreads();
        #pragma unroll
        for (int rep = 0; rep < 2; rep++) {           // K tile, transposed
            int idx = rep * 256 + tid;
            int r = idx >> 4;
            int d4 = (idx & 15) << 2;
            float4 a = *(const float4*)(kr + (size_t)(col0 + r) * DKTOT + h * HDKc + d4);
            Ks[d4 + 0][r] = a.x; Ks[d4 + 1][r] = a.y; Ks[d4 + 2][r] = a.z; Ks[d4 + 3][r] = a.w;
        }
        #pragma unroll
        for (int rep = 0; rep < 4; rep++) {           // V tile
            int idx = rep * 256 + tid;
            int r = idx >> 5;
            int c4 = (idx & 31) << 2;
            *(float4*)&Vs[r][c4] = *(const float4*)(v + (size_t)(col0 + r) * DMODEL + h * HDVc + c4);
        }
        __syncthreads();
        // Stage 1: S(64x32) = Q @ K^T over 64 dims
        float s[4][2] = {{0,0},{0,0},{0,0},{0,0}};
        #pragma unroll 16
        for (int kk = 0; kk < 64; kk++) {
            float4 a = *(const float4*)&Qs[kk][ty * 4];
            float2 b = *(const float2*)&Ks[kk][tx * 2];
            s[0][0] += a.x * b.x; s[0][1] += a.x * b.y;
            s[1][0] += a.y * b.x; s[1][1] += a.y * b.y;
            s[2][0] += a.z * b.x; s[2][1] += a.z * b.y;
            s[3][0] += a.w * b.x; s[3][1] += a.w * b.y;
        }
        // mask (causal + slot gate) and store S transposed+swizzled
        #pragma unroll
        for (int jj = 0; jj < 2; jj++) {
            int j  = tx * 2 + jj;
            int gj = col0 + j;
            int sj = slot[gj * NH + h];
            float4 sv;
            sv.x = (gj <= gi[0] && sj == si[0]) ? s[0][jj] : 0.f;
            sv.y = (gj <= gi[1] && sj == si[1]) ? s[1][jj] : 0.f;
            sv.z = (gj <= gi[2] && sj == si[2]) ? s[2][jj] : 0.f;
            sv.w = (gj <= gi[3] && sj == si[3]) ? s[3][jj] : 0.f;
            *(float4*)&Ss[j][(ty * 4) ^ ((j & 15) << 2)] = sv;
        }
        __syncthreads();
        // Stage 2: O(64x128) += S @ V
        #pragma unroll 8
        for (int kk = 0; kk < 32; kk++) {
            float4 a  = *(const float4*)&Ss[kk][(ty * 4) ^ ((kk & 15) << 2)];
            float4 b0 = *(const float4*)&Vs[kk][tx * 4];
            float4 b1 = *(const float4*)&Vs[kk][64 + tx * 4];
            float av[4] = {a.x, a.y, a.z, a.w};
            float bv[8] = {b0.x, b0.y, b0.z, b0.w, b1.x, b1.y, b1.z, b1.w};
            #pragma unroll
            for (int i = 0; i < 4; i++)
                #pragma unroll
                for (int j = 0; j < 8; j++)
                    acc[i][j] += av[i] * bv[j];
        }
    }
    #pragma unroll
    for (int i = 0; i < 4; i++) {
        size_t row = (size_t)(row0 + ty * 4 + i);
        float4 o0 = make_float4(acc[i][0], acc[i][1], acc[i][2], acc[i][3]);
        float4 o1 = make_float4(acc[i][4], acc[i][5], acc[i][6], acc[i][7]);
        *(float4*)(oa + row * DMODEL + h * HDVc + tx * 4)      = o0;
        *(float4*)(oa + row * DMODEL + h * HDVc + 64 + tx * 4) = o1;
    }
}

// ---------------- per-(l,h) layernorm over 128 dims, then * silu(g) ----------------
__global__ void lngate_kernel(const float* __restrict__ oa, const float* __restrict__ g,
                              float* __restrict__ oc)
{
    int w = (blockIdx.x * blockDim.x + threadIdx.x) >> 5;
    int lane = threadIdx.x & 31;
    int l = w >> 4, h = w & 15;
    size_t base = (size_t)l * DMODEL + h * HDVc + lane * 4;
    float4 xv = *(const float4*)(oa + base);
    float s = xv.x + xv.y + xv.z + xv.w;
    #pragma unroll
    for (int off = 16; off; off >>= 1) s += __shfl_xor_sync(0xffffffffu, s, off);
    float mu = s * (1.f / 128.f);
    float d0 = xv.x - mu, d1 = xv.y - mu, d2 = xv.z - mu, d3 = xv.w - mu;
    float sq = d0 * d0 + d1 * d1 + d2 * d2 + d3 * d3;
    #pragma unroll
    for (int off = 16; off; off >>= 1) sq += __shfl_xor_sync(0xffffffffu, sq, off);
    float inv = rsqrtf(sq * (1.f / 128.f) + 1e-5f);
    float4 gv = *(const float4*)(g + base);
    float4 o;
    o.x = d0 * inv * silu_f(gv.x);
    o.y = d1 * inv * silu_f(gv.y);
    o.z = d2 * inv * silu_f(gv.z);
    o.w = d3 * inv * silu_f(gv.w);
    *(float4*)(oc + base) = o;
}

extern "C" void kernel_launch(void* const* d_in, const int* in_sizes, int n_in,
                              void* d_out, int out_size)
{
    const float* x    = (const float*)d_in[0];
    const float* cw   = (const float*)d_in[1];
    const float* Wq   = (const float*)d_in[2];
    const float* Wk   = (const float*)d_in[3];
    const float* Wv   = (const float*)d_in[4];
    const float* Wg   = (const float*)d_in[5];
    const float* rw   = (const float*)d_in[6];
    const float* Wout = (const float*)d_in[7];
    float* out = (float*)d_out;

    float* S = nullptr;
    cudaGetSymbolAddress((void**)&S, g_scratch);
    float* xc = S;
    float* qb = S + (4u  << 20);
    float* kb = S + (6u  << 20);
    float* vb = S + (8u  << 20);
    float* gb = S + (12u << 20);
    float* qr = S + (16u << 20);
    float* kr = S + (18u << 20);
    float* oa = S + (20u << 20);
    float* oc = S + (24u << 20);
    int*   slot  = (int*)(S + (28u << 20));
    float* score = S + (28u << 20) + 32768;
    float* qsc   = S + (28u << 20) + 65536;

    conv_kernel<<<(LSEQ * DMODEL) / 256, 256>>>(x, cw, xc);
    sgemm_kernel<true ><<<dim3(DKTOT / 128, LSEQ / 128), 256>>>(xc, Wq, qb, DKTOT, DMODEL);
    sgemm_kernel<false><<<dim3(DKTOT / 128, LSEQ / 128), 256>>>(xc, Wk, kb, DKTOT, DMODEL);
    sgemm_kernel<false><<<dim3(DMODEL / 128, LSEQ / 128), 256>>>(xc, Wv, vb, DMODEL, DMODEL);
    sgemm_kernel<false><<<dim3(DMODEL / 128, LSEQ / 128), 256>>>(xc, Wg, gb, DMODEL, DMODEL);
    router_kernel<<<(LSEQ * NH) / 8, 256>>>(vb, rw, slot, score);
    scan_kernel<<<NH, 256>>>(slot, score, qsc);
    rotary_kernel<<<LSEQ, 256>>>(qb, kb, qsc, qr, kr);
    attn_kernel<<<dim3(32, NH), 256>>>(qr, kr, vb, slot, oa);
    lngate_kernel<<<(LSEQ * NH) / 8, 256>>>(oa, gb, oc);
    sgemm_kernel<false><<<dim3(DMODEL / 128, LSEQ / 128), 256>>>(oc, Wout, out, DMODEL, DMODEL);
}

// round 5
// speedup vs baseline: 1.2619x; 1.2619x over previous
#include <cuda_runtime.h>
#include <math.h>

#define LSEQ   2048
#define DMODEL 2048
#define NH     16
#define DKTOT  1024
#define HDKc   64
#define HDVc   128

__device__ float g_scratch[(29u << 20)];

__device__ __forceinline__ float silu_f(float x) { return x / (1.f + expf(-x)); }

__device__ __forceinline__ float f2tf32f(float x) {
    unsigned r;
    asm("cvt.rna.tf32.f32 %0, %1;" : "=r"(r) : "f"(x));
    return __uint_as_float(r);
}
__device__ __forceinline__ void split_tf32(float x, float& hi, float& lo) {
    hi = f2tf32f(x);
    lo = f2tf32f(x - hi);
}

#define MMA_TF32(ACC, AF, BF)                                                   \
    asm volatile(                                                               \
        "mma.sync.aligned.m16n8k8.row.col.f32.tf32.tf32.f32 "                   \
        "{%0,%1,%2,%3},{%4,%5,%6,%7},{%8,%9},{%0,%1,%2,%3};\n"                  \
        : "+f"((ACC)[0]), "+f"((ACC)[1]), "+f"((ACC)[2]), "+f"((ACC)[3])        \
        : "r"((AF)[0]), "r"((AF)[1]), "r"((AF)[2]), "r"((AF)[3]),               \
          "r"((BF)[0]), "r"((BF)[1]))

// ---------------- conv + silu ----------------
__global__ void conv_kernel(const float* __restrict__ x, const float* __restrict__ cw,
                            float* __restrict__ xc)
{
    int idx = blockIdx.x * blockDim.x + threadIdx.x;
    int l = idx >> 11;
    int d = idx & (DMODEL - 1);
    float xp = (l > 0) ? x[idx - DMODEL] : 0.f;
    float v  = xp * cw[2 * d] + x[idx] * cw[2 * d + 1];
    xc[idx] = silu_f(v);
}

// ---------------- split-TF32 tensor GEMM: C = [silu](A @ B), fp32-class accuracy ----------------
// A: M x K row-major, B: K x N row-major. Tile 128x128, k-chunk 8, double-buffered.
#define PA 136
#define PB 136
template <bool SILU>
__global__ void __launch_bounds__(256) tgemm_kernel(
    const float* __restrict__ A, const float* __restrict__ B,
    float* __restrict__ C, int N, int K)
{
    __shared__ float Ah[2][8 * PA];
    __shared__ float Al[2][8 * PA];
    __shared__ float Bh[2][8 * PB];
    __shared__ float Bl[2][8 * PB];

    const int tid  = threadIdx.x;
    const int lane = tid & 31;
    const int warp = tid >> 5;
    const int gid  = lane >> 2;
    const int tig  = lane & 3;
    const int wm   = warp >> 2;        // 0..1 -> 64 rows
    const int wn   = warp & 3;         // 0..3 -> 32 cols
    const int bx = blockIdx.x, by = blockIdx.y;

    const int mA = tid >> 1;                 // A row 0..127
    const int kA = (tid & 1) << 2;           // A k offset 0/4
    const int kB = tid >> 5;                 // B k 0..7
    const int nB = (tid & 31) << 2;          // B n offset

    const float* Ap = A + (size_t)(by * 128 + mA) * K + kA;
    const float* Bp = B + (size_t)kB * N + bx * 128 + nB;

    float acc[4][4][4];
    #pragma unroll
    for (int i = 0; i < 4; i++)
        #pragma unroll
        for (int j = 0; j < 4; j++)
            #pragma unroll
            for (int r = 0; r < 4; r++) acc[i][j][r] = 0.f;

    // prologue: chunk 0 -> buf 0
    float4 a4 = *(const float4*)(Ap);
    float4 b4 = *(const float4*)(Bp);
    {
        float h, l;
        float* d_h = &Ah[0][kA * PA + mA];
        float* d_l = &Al[0][kA * PA + mA];
        split_tf32(a4.x, h, l); d_h[0 * PA] = h; d_l[0 * PA] = l;
        split_tf32(a4.y, h, l); d_h[1 * PA] = h; d_l[1 * PA] = l;
        split_tf32(a4.z, h, l); d_h[2 * PA] = h; d_l[2 * PA] = l;
        split_tf32(a4.w, h, l); d_h[3 * PA] = h; d_l[3 * PA] = l;
        float4 ch, cl;
        split_tf32(b4.x, ch.x, cl.x); split_tf32(b4.y, ch.y, cl.y);
        split_tf32(b4.z, ch.z, cl.z); split_tf32(b4.w, ch.w, cl.w);
        *(float4*)&Bh[0][kB * PB + nB] = ch;
        *(float4*)&Bl[0][kB * PB + nB] = cl;
    }

    int buf = 0;
    for (int k0 = 8; k0 < K; k0 += 8) {
        __syncthreads();
        a4 = *(const float4*)(Ap + k0);
        b4 = *(const float4*)(Bp + (size_t)k0 * N);

        {
            unsigned ah[4][4], al[4][4], bh[4][2], bl[4][2];
            #pragma unroll
            for (int mi = 0; mi < 4; mi++) {
                const int off = tig * PA + wm * 64 + mi * 16 + gid;
                const unsigned* ph = (const unsigned*)&Ah[buf][off];
                const unsigned* pl = (const unsigned*)&Al[buf][off];
                ah[mi][0] = ph[0]; ah[mi][1] = ph[8];
                ah[mi][2] = ph[4 * PA]; ah[mi][3] = ph[4 * PA + 8];
                al[mi][0] = pl[0]; al[mi][1] = pl[8];
                al[mi][2] = pl[4 * PA]; al[mi][3] = pl[4 * PA + 8];
            }
            #pragma unroll
            for (int ni = 0; ni < 4; ni++) {
                const int off = tig * PB + wn * 32 + ni * 8 + gid;
                const unsigned* ph = (const unsigned*)&Bh[buf][off];
                const unsigned* pl = (const unsigned*)&Bl[buf][off];
                bh[ni][0] = ph[0]; bh[ni][1] = ph[4 * PB];
                bl[ni][0] = pl[0]; bl[ni][1] = pl[4 * PB];
            }
            #pragma unroll
            for (int mi = 0; mi < 4; mi++)
                #pragma unroll
                for (int ni = 0; ni < 4; ni++) {
                    MMA_TF32(acc[mi][ni], al[mi], bh[ni]);
                    MMA_TF32(acc[mi][ni], ah[mi], bl[ni]);
                    MMA_TF32(acc[mi][ni], ah[mi], bh[ni]);
                }
        }

        const int nb = buf ^ 1;
        {
            float h, l;
            float* d_h = &Ah[nb][kA * PA + mA];
            float* d_l = &Al[nb][kA * PA + mA];
            split_tf32(a4.x, h, l); d_h[0 * PA] = h; d_l[0 * PA] = l;
            split_tf32(a4.y, h, l); d_h[1 * PA] = h; d_l[1 * PA] = l;
            split_tf32(a4.z, h, l); d_h[2 * PA] = h; d_l[2 * PA] = l;
            split_tf32(a4.w, h, l); d_h[3 * PA] = h; d_l[3 * PA] = l;
            float4 ch, cl;
            split_tf32(b4.x, ch.x, cl.x); split_tf32(b4.y, ch.y, cl.y);
            split_tf32(b4.z, ch.z, cl.z); split_tf32(b4.w, ch.w, cl.w);
            *(float4*)&Bh[nb][kB * PB + nB] = ch;
            *(float4*)&Bl[nb][kB * PB + nB] = cl;
        }
        buf = nb;
    }
    __syncthreads();
    {
        unsigned ah[4][4], al[4][4], bh[4][2], bl[4][2];
        #pragma unroll
        for (int mi = 0; mi < 4; mi++) {
            const int off = tig * PA + wm * 64 + mi * 16 + gid;
            const unsigned* ph = (const unsigned*)&Ah[buf][off];
            const unsigned* pl = (const unsigned*)&Al[buf][off];
            ah[mi][0] = ph[0]; ah[mi][1] = ph[8];
            ah[mi][2] = ph[4 * PA]; ah[mi][3] = ph[4 * PA + 8];
            al[mi][0] = pl[0]; al[mi][1] = pl[8];
            al[mi][2] = pl[4 * PA]; al[mi][3] = pl[4 * PA + 8];
        }
        #pragma unroll
        for (int ni = 0; ni < 4; ni++) {
            const int off = tig * PB + wn * 32 + ni * 8 + gid;
            const unsigned* ph = (const unsigned*)&Bh[buf][off];
            const unsigned* pl = (const unsigned*)&Bl[buf][off];
            bh[ni][0] = ph[0]; bh[ni][1] = ph[4 * PB];
            bl[ni][0] = pl[0]; bl[ni][1] = pl[4 * PB];
        }
        #pragma unroll
        for (int mi = 0; mi < 4; mi++)
            #pragma unroll
            for (int ni = 0; ni < 4; ni++) {
                MMA_TF32(acc[mi][ni], al[mi], bh[ni]);
                MMA_TF32(acc[mi][ni], ah[mi], bl[ni]);
                MMA_TF32(acc[mi][ni], ah[mi], bh[ni]);
            }
    }

    #pragma unroll
    for (int mi = 0; mi < 4; mi++) {
        #pragma unroll
        for (int ni = 0; ni < 4; ni++) {
            int r = by * 128 + wm * 64 + mi * 16 + gid;
            int c = bx * 128 + wn * 32 + ni * 8 + tig * 2;
            float2 v0, v1;
            if (SILU) {
                v0 = make_float2(silu_f(acc[mi][ni][0]), silu_f(acc[mi][ni][1]));
                v1 = make_float2(silu_f(acc[mi][ni][2]), silu_f(acc[mi][ni][3]));
            } else {
                v0 = make_float2(acc[mi][ni][0], acc[mi][ni][1]);
                v1 = make_float2(acc[mi][ni][2], acc[mi][ni][3]);
            }
            *(float2*)(C + (size_t)r * N + c)       = v0;
            *(float2*)(C + (size_t)(r + 8) * N + c) = v1;
        }
    }
}

// ---------------- router ----------------
__global__ void router_kernel(const float* __restrict__ v, const float* __restrict__ rw,
                              int* __restrict__ slot, float* __restrict__ score)
{
    int w = (blockIdx.x * blockDim.x + threadIdx.x) >> 5;
    int lane = threadIdx.x & 31;
    int l = w >> 4, h = w & 15;
    const float* vp = v + (size_t)l * DMODEL + h * HDVc;
    float4 vv = *(const float4*)(vp + lane * 4);
    const float* rp = rw + h * HDVc * 2 + lane * 8;
    float4 r0 = *(const float4*)(rp);
    float4 r1 = *(const float4*)(rp + 4);
    float l0 = vv.x * r0.x + vv.y * r0.z + vv.z * r1.x + vv.w * r1.z;
    float l1 = vv.x * r0.y + vv.y * r0.w + vv.z * r1.y + vv.w * r1.w;
    #pragma unroll
    for (int off = 16; off; off >>= 1) {
        l0 += __shfl_xor_sync(0xffffffffu, l0, off);
        l1 += __shfl_xor_sync(0xffffffffu, l1, off);
    }
    if (lane == 0) {
        int s = (l1 > l0) ? 1 : 0;
        slot[l * NH + h]  = s;
        score[l * NH + h] = 1.f / (1.f + expf(-fabsf(l0 - l1)));
    }
}

// ---------------- per-head scan ----------------
__global__ void scan_kernel(const int* __restrict__ slot, const float* __restrict__ score,
                            float* __restrict__ qscale)
{
    __shared__ int   sl[LSEQ];
    __shared__ float nm[LSEQ];
    int h = blockIdx.x;
    for (int i = threadIdx.x; i < LSEQ; i += blockDim.x) sl[i] = slot[i * NH + h];
    __syncthreads();
    if (threadIdx.x == 0) {
        int c0 = 0, c1 = 0;
        for (int i = 0; i < LSEQ; i++) {
            int c = sl[i] ? ++c1 : ++c0;
            nm[i] = 1.f / (float)c;
        }
    }
    __syncthreads();
    for (int i = threadIdx.x; i < LSEQ; i += blockDim.x)
        qscale[i * NH + h] = score[i * NH + h] * nm[i] * 0.125f;
}

// ---------------- rotary ----------------
__global__ void rotary_kernel(const float* __restrict__ q, const float* __restrict__ k,
                              const float* __restrict__ qscale,
                              float* __restrict__ qr, float* __restrict__ kr)
{
    __shared__ float cs[32], sn[32];
    int l = blockIdx.x;
    if (threadIdx.x < 32) {
        float invf = expf(-(float)threadIdx.x * (logf(10000.f) / 32.f));
        float f = (float)l * invf;
        sincosf(f, &sn[threadIdx.x], &cs[threadIdx.x]);
    }
    __syncthreads();
    for (int it = threadIdx.x; it < 2 * DKTOT; it += blockDim.x) {
        int isK = it >> 10;
        int idx = it & 1023;
        int h = idx >> 6, d = idx & 63;
        const float* src = isK ? k : q;
        size_t base = (size_t)l * DKTOT + h * HDKc;
        float val;
        if (d < 32) val = src[base + d] * cs[d]      - src[base + d + 32] * sn[d];
        else        val = src[base + d] * cs[d - 32] + src[base + d - 32] * sn[d - 32];
        if (isK) kr[base + d] = val;
        else     qr[base + d] = val * qscale[l * NH + h];
    }
}

// ---------------- gated causal attention (fp32) ----------------
__global__ void __launch_bounds__(256) attn_kernel(
    const float* __restrict__ qr, const float* __restrict__ kr,
    const float* __restrict__ v, const int* __restrict__ slot,
    float* __restrict__ oa)
{
    __shared__ float Qs[64][64];
    __shared__ float Ks[64][32];
    __shared__ float Vs[32][128];
    __shared__ float Ss[32][64];
    const int it  = 31 - blockIdx.x;
    const int h   = blockIdx.y;
    const int tid = threadIdx.x;
    const int tx = tid & 15, ty = tid >> 4;
    const int row0 = it * 64;

    #pragma unroll
    for (int rep = 0; rep < 4; rep++) {
        int idx = rep * 256 + tid;
        int r = idx >> 4;
        int d4 = (idx & 15) << 2;
        float4 a = *(const float4*)(qr + (size_t)(row0 + r) * DKTOT + h * HDKc + d4);
        Qs[d4 + 0][r] = a.x; Qs[d4 + 1][r] = a.y; Qs[d4 + 2][r] = a.z; Qs[d4 + 3][r] = a.w;
    }
    int si[4], gi[4];
    #pragma unroll
    for (int i = 0; i < 4; i++) { gi[i] = row0 + ty * 4 + i; si[i] = slot[gi[i] * NH + h]; }

    float acc[4][8];
    #pragma unroll
    for (int i = 0; i < 4; i++)
        #pragma unroll
        for (int j = 0; j < 8; j++) acc[i][j] = 0.f;

    const int njt = 2 * it + 2;
    for (int jt = 0; jt < njt; jt++) {
        const int col0 = jt * 32;
        __syncthreads();
        #pragma unroll
        for (int rep = 0; rep < 2; rep++) {
            int idx = rep * 256 + tid;
            int r = idx >> 4;
            int d4 = (idx & 15) << 2;
            float4 a = *(const float4*)(kr + (size_t)(col0 + r) * DKTOT + h * HDKc + d4);
            Ks[d4 + 0][r] = a.x; Ks[d4 + 1][r] = a.y; Ks[d4 + 2][r] = a.z; Ks[d4 + 3][r] = a.w;
        }
        #pragma unroll
        for (int rep = 0; rep < 4; rep++) {
            int idx = rep * 256 + tid;
            int r = idx >> 5;
            int c4 = (idx & 31) << 2;
            *(float4*)&Vs[r][c4] = *(const float4*)(v + (size_t)(col0 + r) * DMODEL + h * HDVc + c4);
        }
        __syncthreads();
        float s[4][2] = {{0,0},{0,0},{0,0},{0,0}};
        #pragma unroll 16
        for (int kk = 0; kk < 64; kk++) {
            float4 a = *(const float4*)&Qs[kk][ty * 4];
            float2 b = *(const float2*)&Ks[kk][tx * 2];
            s[0][0] += a.x * b.x; s[0][1] += a.x * b.y;
            s[1][0] += a.y * b.x; s[1][1] += a.y * b.y;
            s[2][0] += a.z * b.x; s[2][1] += a.z * b.y;
            s[3][0] += a.w * b.x; s[3][1] += a.w * b.y;
        }
        #pragma unroll
        for (int jj = 0; jj < 2; jj++) {
            int j  = tx * 2 + jj;
            int gj = col0 + j;
            int sj = slot[gj * NH + h];
            float4 sv;
            sv.x = (gj <= gi[0] && sj == si[0]) ? s[0][jj] : 0.f;
            sv.y = (gj <= gi[1] && sj == si[1]) ? s[1][jj] : 0.f;
            sv.z = (gj <= gi[2] && sj == si[2]) ? s[2][jj] : 0.f;
            sv.w = (gj <= gi[3] && sj == si[3]) ? s[3][jj] : 0.f;
            *(float4*)&Ss[j][(ty * 4) ^ ((j & 15) << 2)] = sv;
        }
        __syncthreads();
        #pragma unroll 8
        for (int kk = 0; kk < 32; kk++) {
            float4 a  = *(const float4*)&Ss[kk][(ty * 4) ^ ((kk & 15) << 2)];
            float4 b0 = *(const float4*)&Vs[kk][tx * 4];
            float4 b1 = *(const float4*)&Vs[kk][64 + tx * 4];
            float av[4] = {a.x, a.y, a.z, a.w};
            float bv[8] = {b0.x, b0.y, b0.z, b0.w, b1.x, b1.y, b1.z, b1.w};
            #pragma unroll
            for (int i = 0; i < 4; i++)
                #pragma unroll
                for (int j = 0; j < 8; j++)
                    acc[i][j] += av[i] * bv[j];
        }
    }
    #pragma unroll
    for (int i = 0; i < 4; i++) {
        size_t row = (size_t)(row0 + ty * 4 + i);
        float4 o0 = make_float4(acc[i][0], acc[i][1], acc[i][2], acc[i][3]);
        float4 o1 = make_float4(acc[i][4], acc[i][5], acc[i][6], acc[i][7]);
        *(float4*)(oa + row * DMODEL + h * HDVc + tx * 4)      = o0;
        *(float4*)(oa + row * DMODEL + h * HDVc + 64 + tx * 4) = o1;
    }
}

// ---------------- layernorm + gate ----------------
__global__ void lngate_kernel(const float* __restrict__ oa, const float* __restrict__ g,
                              float* __restrict__ oc)
{
    int w = (blockIdx.x * blockDim.x + threadIdx.x) >> 5;
    int lane = threadIdx.x & 31;
    int l = w >> 4, h = w & 15;
    size_t base = (size_t)l * DMODEL + h * HDVc + lane * 4;
    float4 xv = *(const float4*)(oa + base);
    float s = xv.x + xv.y + xv.z + xv.w;
    #pragma unroll
    for (int off = 16; off; off >>= 1) s += __shfl_xor_sync(0xffffffffu, s, off);
    float mu = s * (1.f / 128.f);
    float d0 = xv.x - mu, d1 = xv.y - mu, d2 = xv.z - mu, d3 = xv.w - mu;
    float sq = d0 * d0 + d1 * d1 + d2 * d2 + d3 * d3;
    #pragma unroll
    for (int off = 16; off; off >>= 1) sq += __shfl_xor_sync(0xffffffffu, sq, off);
    float inv = rsqrtf(sq * (1.f / 128.f) + 1e-5f);
    float4 gv = *(const float4*)(g + base);
    float4 o;
    o.x = d0 * inv * silu_f(gv.x);
    o.y = d1 * inv * silu_f(gv.y);
    o.z = d2 * inv * silu_f(gv.z);
    o.w = d3 * inv * silu_f(gv.w);
    *(float4*)(oc + base) = o;
}

extern "C" void kernel_launch(void* const* d_in, const int* in_sizes, int n_in,
                              void* d_out, int out_size)
{
    const float* x    = (const float*)d_in[0];
    const float* cw   = (const float*)d_in[1];
    const float* Wq   = (const float*)d_in[2];
    const float* Wk   = (const float*)d_in[3];
    const float* Wv   = (const float*)d_in[4];
    const float* Wg   = (const float*)d_in[5];
    const float* rw   = (const float*)d_in[6];
    const float* Wout = (const float*)d_in[7];
    float* out = (float*)d_out;

    float* S = nullptr;
    cudaGetSymbolAddress((void**)&S, g_scratch);
    float* xc = S;
    float* qb = S + (4u  << 20);
    float* kb = S + (6u  << 20);
    float* vb = S + (8u  << 20);
    float* gb = S + (12u << 20);
    float* qr = S + (16u << 20);
    float* kr = S + (18u << 20);
    float* oa = S + (20u << 20);
    float* oc = S + (24u << 20);
    int*   slot  = (int*)(S + (28u << 20));
    float* score = S + (28u << 20) + 32768;
    float* qsc   = S + (28u << 20) + 65536;

    conv_kernel<<<(LSEQ * DMODEL) / 256, 256>>>(x, cw, xc);
    tgemm_kernel<true ><<<dim3(DKTOT / 128, LSEQ / 128), 256>>>(xc, Wq, qb, DKTOT, DMODEL);
    tgemm_kernel<false><<<dim3(DKTOT / 128, LSEQ / 128), 256>>>(xc, Wk, kb, DKTOT, DMODEL);
    tgemm_kernel<false><<<dim3(DMODEL / 128, LSEQ / 128), 256>>>(xc, Wv, vb, DMODEL, DMODEL);
    tgemm_kernel<false><<<dim3(DMODEL / 128, LSEQ / 128), 256>>>(xc, Wg, gb, DMODEL, DMODEL);
    router_kernel<<<(LSEQ * NH) / 8, 256>>>(vb, rw, slot, score);
    scan_kernel<<<NH, 256>>>(slot, score, qsc);
    rotary_kernel<<<LSEQ, 256>>>(qb, kb, qsc, qr, kr);
    attn_kernel<<<dim3(32, NH), 256>>>(qr, kr, vb, slot, oa);
    lngate_kernel<<<(LSEQ * NH) / 8, 256>>>(oa, gb, oc);
    tgemm_kernel<false><<<dim3(DMODEL / 128, LSEQ / 128), 256>>>(oc, Wout, out, DMODEL, DMODEL);
}

// round 6
// speedup vs baseline: 1.2984x; 1.0289x over previous
#include <cuda_runtime.h>
#include <math.h>

#define LSEQ   2048
#define DMODEL 2048
#define NH     16

#define MEG (1u << 20)
__device__ float g_scratch[82u * MEG];

__device__ __forceinline__ float silu_f(float x) { return x / (1.f + expf(-x)); }

__device__ __forceinline__ float f2tf32f(float x) {
    unsigned r;
    asm("cvt.rna.tf32.f32 %0, %1;" : "=r"(r) : "f"(x));
    return __uint_as_float(r);
}
__device__ __forceinline__ void split_tf32(float x, float& hi, float& lo) {
    hi = f2tf32f(x);
    lo = f2tf32f(x - hi);
}

#define MMA_TF32(ACC, AF, BF)                                                   \
    asm volatile(                                                               \
        "mma.sync.aligned.m16n8k8.row.col.f32.tf32.tf32.f32 "                   \
        "{%0,%1,%2,%3},{%4,%5,%6,%7},{%8,%9},{%0,%1,%2,%3};\n"                  \
        : "+f"((ACC)[0]), "+f"((ACC)[1]), "+f"((ACC)[2]), "+f"((ACC)[3])        \
        : "r"((AF)[0]), "r"((AF)[1]), "r"((AF)[2]), "r"((AF)[3]),               \
          "r"((BF)[0]), "r"((BF)[1]))

// ---------------- conv + silu, write split ----------------
__global__ void conv_split_kernel(const float* __restrict__ x, const float* __restrict__ cw,
                                  float* __restrict__ xh, float* __restrict__ xl)
{
    int idx = blockIdx.x * blockDim.x + threadIdx.x;
    int l = idx >> 11;
    int d = idx & (DMODEL - 1);
    float xp = (l > 0) ? x[idx - DMODEL] : 0.f;
    float v  = silu_f(xp * cw[2 * d] + x[idx] * cw[2 * d + 1]);
    float hi, lo; split_tf32(v, hi, lo);
    xh[idx] = hi; xl[idx] = lo;
}

// ---------------- concat Wq|Wk and split ----------------
__global__ void qkcat_split_kernel(const float* __restrict__ Wq, const float* __restrict__ Wk,
                                   float* __restrict__ wh, float* __restrict__ wl)
{
    int idx = blockIdx.x * blockDim.x + threadIdx.x;  // 0..4M
    int k = idx >> 11;
    int n = idx & 2047;
    float w = (n < 1024) ? Wq[k * 1024 + n] : Wk[k * 1024 + (n - 1024)];
    float hi, lo; split_tf32(w, hi, lo);
    wh[idx] = hi; wl[idx] = lo;
}

// ---------------- generic split ----------------
__global__ void split_kernel(const float* __restrict__ s, float* __restrict__ hi_o,
                             float* __restrict__ lo_o)
{
    int idx = blockIdx.x * blockDim.x + threadIdx.x;
    float hi, lo; split_tf32(s[idx], hi, lo);
    hi_o[idx] = hi; lo_o[idx] = lo;
}

// ---------------- split-TF32 GEMM on pre-split operands ----------------
#define PA 136
#define PB 136
__global__ void __launch_bounds__(256) tgemm_ps(
    const float* __restrict__ Agh, const float* __restrict__ Agl,
    const float* __restrict__ Bgh, const float* __restrict__ Bgl,
    float* __restrict__ C, int N, int K)
{
    __shared__ float Ah[2][8 * PA];
    __shared__ float Al[2][8 * PA];
    __shared__ float Bh[2][8 * PB];
    __shared__ float Bl[2][8 * PB];

    const int tid  = threadIdx.x;
    const int lane = tid & 31;
    const int warp = tid >> 5;
    const int gid  = lane >> 2;
    const int tig  = lane & 3;
    const int wm   = warp >> 2;
    const int wn   = warp & 3;
    const int bx = blockIdx.x, by = blockIdx.y;

    const int mA = tid >> 1;
    const int kA = (tid & 1) << 2;
    const int kB = tid >> 5;
    const int nB = (tid & 31) << 2;

    const size_t aoff = (size_t)(by * 128 + mA) * K + kA;
    const size_t boff = (size_t)kB * N + bx * 128 + nB;

    float acc[4][4][4];
    #pragma unroll
    for (int i = 0; i < 4; i++)
        #pragma unroll
        for (int j = 0; j < 4; j++)
            #pragma unroll
            for (int r = 0; r < 4; r++) acc[i][j][r] = 0.f;

    float4 a4h = *(const float4*)(Agh + aoff);
    float4 a4l = *(const float4*)(Agl + aoff);
    float4 b4h = *(const float4*)(Bgh + boff);
    float4 b4l = *(const float4*)(Bgl + boff);
    {
        float* dh = &Ah[0][kA * PA + mA];
        float* dl = &Al[0][kA * PA + mA];
        dh[0*PA]=a4h.x; dh[1*PA]=a4h.y; dh[2*PA]=a4h.z; dh[3*PA]=a4h.w;
        dl[0*PA]=a4l.x; dl[1*PA]=a4l.y; dl[2*PA]=a4l.z; dl[3*PA]=a4l.w;
        *(float4*)&Bh[0][kB * PB + nB] = b4h;
        *(float4*)&Bl[0][kB * PB + nB] = b4l;
    }

    int buf = 0;
    for (int k0 = 8; k0 < K; k0 += 8) {
        __syncthreads();
        a4h = *(const float4*)(Agh + aoff + k0);
        a4l = *(const float4*)(Agl + aoff + k0);
        b4h = *(const float4*)(Bgh + boff + (size_t)k0 * N);
        b4l = *(const float4*)(Bgl + boff + (size_t)k0 * N);

        {
            unsigned ah[4][4], al[4][4], bh[4][2], bl[4][2];
            #pragma unroll
            for (int mi = 0; mi < 4; mi++) {
                const int off = tig * PA + wm * 64 + mi * 16 + gid;
                const unsigned* ph = (const unsigned*)&Ah[buf][off];
                const unsigned* pl = (const unsigned*)&Al[buf][off];
                ah[mi][0] = ph[0]; ah[mi][1] = ph[8];
                ah[mi][2] = ph[4 * PA]; ah[mi][3] = ph[4 * PA + 8];
                al[mi][0] = pl[0]; al[mi][1] = pl[8];
                al[mi][2] = pl[4 * PA]; al[mi][3] = pl[4 * PA + 8];
            }
            #pragma unroll
            for (int ni = 0; ni < 4; ni++) {
                const int off = tig * PB + wn * 32 + ni * 8 + gid;
                const unsigned* ph = (const unsigned*)&Bh[buf][off];
                const unsigned* pl = (const unsigned*)&Bl[buf][off];
                bh[ni][0] = ph[0]; bh[ni][1] = ph[4 * PB];
                bl[ni][0] = pl[0]; bl[ni][1] = pl[4 * PB];
            }
            #pragma unroll
            for (int mi = 0; mi < 4; mi++)
                #pragma unroll
                for (int ni = 0; ni < 4; ni++) {
                    MMA_TF32(acc[mi][ni], al[mi], bh[ni]);
                    MMA_TF32(acc[mi][ni], ah[mi], bl[ni]);
                    MMA_TF32(acc[mi][ni], ah[mi], bh[ni]);
                }
        }

        const int nb = buf ^ 1;
        {
            float* dh = &Ah[nb][kA * PA + mA];
            float* dl = &Al[nb][kA * PA + mA];
            dh[0*PA]=a4h.x; dh[1*PA]=a4h.y; dh[2*PA]=a4h.z; dh[3*PA]=a4h.w;
            dl[0*PA]=a4l.x; dl[1*PA]=a4l.y; dl[2*PA]=a4l.z; dl[3*PA]=a4l.w;
            *(float4*)&Bh[nb][kB * PB + nB] = b4h;
            *(float4*)&Bl[nb][kB * PB + nB] = b4l;
        }
        buf = nb;
    }
    __syncthreads();
    {
        unsigned ah[4][4], al[4][4], bh[4][2], bl[4][2];
        #pragma unroll
        for (int mi = 0; mi < 4; mi++) {
            const int off = tig * PA + wm * 64 + mi * 16 + gid;
            const unsigned* ph = (const unsigned*)&Ah[buf][off];
            const unsigned* pl = (const unsigned*)&Al[buf][off];
            ah[mi][0] = ph[0]; ah[mi][1] = ph[8];
            ah[mi][2] = ph[4 * PA]; ah[mi][3] = ph[4 * PA + 8];
            al[mi][0] = pl[0]; al[mi][1] = pl[8];
            al[mi][2] = pl[4 * PA]; al[mi][3] = pl[4 * PA + 8];
        }
        #pragma unroll
        for (int ni = 0; ni < 4; ni++) {
            const int off = tig * PB + wn * 32 + ni * 8 + gid;
            const unsigned* ph = (const unsigned*)&Bh[buf][off];
            const unsigned* pl = (const unsigned*)&Bl[buf][off];
            bh[ni][0] = ph[0]; bh[ni][1] = ph[4 * PB];
            bl[ni][0] = pl[0]; bl[ni][1] = pl[4 * PB];
        }
        #pragma unroll
        for (int mi = 0; mi < 4; mi++)
            #pragma unroll
            for (int ni = 0; ni < 4; ni++) {
                MMA_TF32(acc[mi][ni], al[mi], bh[ni]);
                MMA_TF32(acc[mi][ni], ah[mi], bl[ni]);
                MMA_TF32(acc[mi][ni], ah[mi], bh[ni]);
            }
    }

    #pragma unroll
    for (int mi = 0; mi < 4; mi++) {
        #pragma unroll
        for (int ni = 0; ni < 4; ni++) {
            int r = by * 128 + wm * 64 + mi * 16 + gid;
            int c = bx * 128 + wn * 32 + ni * 8 + tig * 2;
            *(float2*)(C + (size_t)r * N + c)       = make_float2(acc[mi][ni][0], acc[mi][ni][1]);
            *(float2*)(C + (size_t)(r + 8) * N + c) = make_float2(acc[mi][ni][2], acc[mi][ni][3]);
        }
    }
}

// ---------------- router ----------------
__global__ void router_kernel(const float* __restrict__ v, const float* __restrict__ rw,
                              int* __restrict__ slot, float* __restrict__ score)
{
    int w = (blockIdx.x * blockDim.x + threadIdx.x) >> 5;
    int lane = threadIdx.x & 31;
    int l = w >> 4, h = w & 15;
    const float* vp = v + (size_t)l * DMODEL + h * 128;
    float4 vv = *(const float4*)(vp + lane * 4);
    const float* rp = rw + h * 256 + lane * 8;
    float4 r0 = *(const float4*)(rp);
    float4 r1 = *(const float4*)(rp + 4);
    float l0 = vv.x * r0.x + vv.y * r0.z + vv.z * r1.x + vv.w * r1.z;
    float l1 = vv.x * r0.y + vv.y * r0.w + vv.z * r1.y + vv.w * r1.w;
    #pragma unroll
    for (int off = 16; off; off >>= 1) {
        l0 += __shfl_xor_sync(0xffffffffu, l0, off);
        l1 += __shfl_xor_sync(0xffffffffu, l1, off);
    }
    if (lane == 0) {
        slot[l * NH + h]  = (l1 > l0) ? 1 : 0;
        score[l * NH + h] = 1.f / (1.f + expf(-fabsf(l0 - l1)));
    }
}

// ---------------- per-head scan ----------------
__global__ void scan_kernel(const int* __restrict__ slot, const float* __restrict__ score,
                            float* __restrict__ qscale)
{
    __shared__ int   sl[LSEQ];
    __shared__ float nm[LSEQ];
    int h = blockIdx.x;
    for (int i = threadIdx.x; i < LSEQ; i += blockDim.x) sl[i] = slot[i * NH + h];
    __syncthreads();
    if (threadIdx.x == 0) {
        int c0 = 0, c1 = 0;
        for (int i = 0; i < LSEQ; i++) {
            int c = sl[i] ? ++c1 : ++c0;
            nm[i] = 1.f / (float)c;
        }
    }
    __syncthreads();
    for (int i = threadIdx.x; i < LSEQ; i += blockDim.x)
        qscale[i * NH + h] = score[i * NH + h] * nm[i] * 0.125f;
}

// ---------------- rotary: silu(q), rotate, scale, split ----------------
__global__ void rotary_kernel(const float* __restrict__ qk, const float* __restrict__ qsc,
                              float* __restrict__ qrh, float* __restrict__ qrl,
                              float* __restrict__ krh, float* __restrict__ krl)
{
    __shared__ float cs[32], sn[32];
    int l = blockIdx.x;
    if (threadIdx.x < 32) {
        float invf = expf(-(float)threadIdx.x * (logf(10000.f) / 32.f));
        float f = (float)l * invf;
        sincosf(f, &sn[threadIdx.x], &cs[threadIdx.x]);
    }
    __syncthreads();
    for (int it = threadIdx.x; it < 2048; it += blockDim.x) {
        int isK = it >> 10;
        int idx = it & 1023;
        int h = idx >> 6, d = idx & 63;
        size_t base = (size_t)l * 2048 + (size_t)isK * 1024 + h * 64;
        float a = qk[base + d];
        float b = (d < 32) ? qk[base + d + 32] : qk[base + d - 32];
        if (!isK) { a = silu_f(a); b = silu_f(b); }
        float val = (d < 32) ? (a * cs[d] - b * sn[d]) : (a * cs[d - 32] + b * sn[d - 32]);
        if (!isK) val *= qsc[l * NH + h];
        float hi, lo; split_tf32(val, hi, lo);
        size_t o = (size_t)l * 1024 + h * 64 + d;
        if (isK) { krh[o] = hi; krl[o] = lo; }
        else     { qrh[o] = hi; qrl[o] = lo; }
    }
}

// ---------------- attention: split-TF32 mma, S^T formulation ----------------
// smem (floats): Ksh[32*72], Ksl[32*72], Vsh[32*136], Vsl[32*136], Ssh[32*72], Ssl[32*72]
#define ATN_SMEM_FLOATS (2304*2 + 4352*2 + 2304*2)
__global__ void __launch_bounds__(256) attn_kernel(
    const float* __restrict__ qh, const float* __restrict__ ql,
    const float* __restrict__ kh, const float* __restrict__ kl,
    const float* __restrict__ vh, const float* __restrict__ vl,
    const int* __restrict__ slot, float* __restrict__ oa)
{
    extern __shared__ float sm[];
    float* Ksh = sm;
    float* Ksl = sm + 2304;
    float* Vsh = sm + 4608;
    float* Vsl = sm + 8960;
    float* Ssh = sm + 13312;
    float* Ssl = sm + 15616;
    __shared__ int slq[64];
    __shared__ int slk[32];

    const int it   = 31 - blockIdx.x;
    const int h    = blockIdx.y;
    const int tid  = threadIdx.x;
    const int lane = tid & 31, warp = tid >> 5;
    const int gid  = lane >> 2, tig = lane & 3;
    const int row0 = it * 64;
    const int hq = h * 64;
    const int hv = h * 128;
    const int wm1 = warp >> 2, wn1 = warp & 3;   // stage1: j-16tile, i-16region
    const int wm2 = warp >> 1, wn2 = warp & 1;   // stage2: i-16tile, 64 v-cols

    if (tid < 64) slq[tid] = slot[(row0 + tid) * NH + h];

    // Q B-fragments (registers), i-region = wn1*16
    unsigned bqh[8][2][2], bql[8][2][2];
    #pragma unroll
    for (int kk = 0; kk < 8; kk++)
        #pragma unroll
        for (int t = 0; t < 2; t++) {
            size_t off = (size_t)(row0 + wn1 * 16 + t * 8 + gid) * 1024 + hq + kk * 8 + tig;
            bqh[kk][t][0] = __float_as_uint(qh[off]);
            bqh[kk][t][1] = __float_as_uint(qh[off + 4]);
            bql[kk][t][0] = __float_as_uint(ql[off]);
            bql[kk][t][1] = __float_as_uint(ql[off + 4]);
        }

    float oacc[8][4];
    #pragma unroll
    for (int ni = 0; ni < 8; ni++)
        #pragma unroll
        for (int r = 0; r < 4; r++) oacc[ni][r] = 0.f;

    const int njt = 2 * it + 2;
    for (int jt = 0; jt < njt; jt++) {
        const int col0 = jt * 32;
        __syncthreads();
        #pragma unroll
        for (int rep = 0; rep < 2; rep++) {          // K tiles 32x64 hi/lo
            int e = rep * 256 + tid;
            int j = e >> 4, d4 = (e & 15) << 2;
            size_t go = (size_t)(col0 + j) * 1024 + hq + d4;
            *(float4*)&Ksh[j * 72 + d4] = *(const float4*)(kh + go);
            *(float4*)&Ksl[j * 72 + d4] = *(const float4*)(kl + go);
        }
        #pragma unroll
        for (int rep = 0; rep < 4; rep++) {          // V tiles 32x128 hi/lo
            int e = rep * 256 + tid;
            int j = e >> 5, c4 = (e & 31) << 2;
            size_t go = (size_t)(col0 + j) * 2048 + hv + c4;
            *(float4*)&Vsh[j * 136 + c4] = *(const float4*)(vh + go);
            *(float4*)&Vsl[j * 136 + c4] = *(const float4*)(vl + go);
        }
        if (tid < 32) slk[tid] = slot[(col0 + tid) * NH + h];
        __syncthreads();

        // stage1: S^T(32x64) = K @ Q^T, split-TF32
        float sacc[2][4] = {{0.f,0.f,0.f,0.f},{0.f,0.f,0.f,0.f}};
        #pragma unroll
        for (int kk = 0; kk < 8; kk++) {
            unsigned akh[4], akl[4];
            const int ao = (wm1 * 16 + gid) * 72 + kk * 8 + tig;
            akh[0] = __float_as_uint(Ksh[ao]);
            akh[1] = __float_as_uint(Ksh[ao + 8 * 72]);
            akh[2] = __float_as_uint(Ksh[ao + 4]);
            akh[3] = __float_as_uint(Ksh[ao + 8 * 72 + 4]);
            akl[0] = __float_as_uint(Ksl[ao]);
            akl[1] = __float_as_uint(Ksl[ao + 8 * 72]);
            akl[2] = __float_as_uint(Ksl[ao + 4]);
            akl[3] = __float_as_uint(Ksl[ao + 8 * 72 + 4]);
            #pragma unroll
            for (int t = 0; t < 2; t++) {
                MMA_TF32(sacc[t], akl, bqh[kk][t]);
                MMA_TF32(sacc[t], akh, bql[kk][t]);
                MMA_TF32(sacc[t], akh, bqh[kk][t]);
            }
        }
        // mask (causal + slot) in registers, split, store S^T [j][i]
        {
            int jl0 = wm1 * 16 + gid, jl1 = jl0 + 8;
            int jg0 = col0 + jl0, jg1 = col0 + jl1;
            int sj0 = slk[jl0], sj1 = slk[jl1];
            #pragma unroll
            for (int t = 0; t < 2; t++) {
                int ilc = wn1 * 16 + t * 8 + tig * 2;
                int ig = row0 + ilc;
                int si0 = slq[ilc], si1 = slq[ilc + 1];
                float c0 = (jg0 <= ig     && sj0 == si0) ? sacc[t][0] : 0.f;
                float c1 = (jg0 <= ig + 1 && sj0 == si1) ? sacc[t][1] : 0.f;
                float c2 = (jg1 <= ig     && sj1 == si0) ? sacc[t][2] : 0.f;
                float c3 = (jg1 <= ig + 1 && sj1 == si1) ? sacc[t][3] : 0.f;
                float h0,l0,h1,l1,h2,l2,h3,l3;
                split_tf32(c0,h0,l0); split_tf32(c1,h1,l1);
                split_tf32(c2,h2,l2); split_tf32(c3,h3,l3);
                *(float2*)&Ssh[jl0 * 72 + ilc] = make_float2(h0, h1);
                *(float2*)&Ssl[jl0 * 72 + ilc] = make_float2(l0, l1);
                *(float2*)&Ssh[jl1 * 72 + ilc] = make_float2(h2, h3);
                *(float2*)&Ssl[jl1 * 72 + ilc] = make_float2(l2, l3);
            }
        }
        __syncthreads();

        // stage2: O(64x128) += S @ V, split-TF32
        #pragma unroll
        for (int ks = 0; ks < 4; ks++) {
            unsigned ash[4], asl[4];
            const int ao = (ks * 8 + tig) * 72 + wm2 * 16 + gid;
            ash[0] = __float_as_uint(Ssh[ao]);
            ash[1] = __float_as_uint(Ssh[ao + 8]);
            ash[2] = __float_as_uint(Ssh[ao + 4 * 72]);
            ash[3] = __float_as_uint(Ssh[ao + 4 * 72 + 8]);
            asl[0] = __float_as_uint(Ssl[ao]);
            asl[1] = __float_as_uint(Ssl[ao + 8]);
            asl[2] = __float_as_uint(Ssl[ao + 4 * 72]);
            asl[3] = __float_as_uint(Ssl[ao + 4 * 72 + 8]);
            #pragma unroll
            for (int ni = 0; ni < 8; ni++) {
                unsigned bvh[2], bvl[2];
                const int bo = (ks * 8 + tig) * 136 + wn2 * 64 + ni * 8 + gid;
                bvh[0] = __float_as_uint(Vsh[bo]);
                bvh[1] = __float_as_uint(Vsh[bo + 4 * 136]);
                bvl[0] = __float_as_uint(Vsl[bo]);
                bvl[1] = __float_as_uint(Vsl[bo + 4 * 136]);
                MMA_TF32(oacc[ni], asl, bvh);
                MMA_TF32(oacc[ni], ash, bvl);
                MMA_TF32(oacc[ni], ash, bvh);
            }
        }
    }
    #pragma unroll
    for (int ni = 0; ni < 8; ni++) {
        int i0 = row0 + wm2 * 16 + gid;
        int c = hv + wn2 * 64 + ni * 8 + tig * 2;
        *(float2*)(oa + (size_t)i0 * 2048 + c)       = make_float2(oacc[ni][0], oacc[ni][1]);
        *(float2*)(oa + (size_t)(i0 + 8) * 2048 + c) = make_float2(oacc[ni][2], oacc[ni][3]);
    }
}

// ---------------- layernorm + gate, write split ----------------
__global__ void lngate_kernel(const float* __restrict__ oa, const float* __restrict__ g,
                              float* __restrict__ och, float* __restrict__ ocl)
{
    int w = (blockIdx.x * blockDim.x + threadIdx.x) >> 5;
    int lane = threadIdx.x & 31;
    int l = w >> 4, h = w & 15;
    size_t base = (size_t)l * DMODEL + h * 128 + lane * 4;
    float4 xv = *(const float4*)(oa + base);
    float s = xv.x + xv.y + xv.z + xv.w;
    #pragma unroll
    for (int off = 16; off; off >>= 1) s += __shfl_xor_sync(0xffffffffu, s, off);
    float mu = s * (1.f / 128.f);
    float d0 = xv.x - mu, d1 = xv.y - mu, d2 = xv.z - mu, d3 = xv.w - mu;
    float sq = d0 * d0 + d1 * d1 + d2 * d2 + d3 * d3;
    #pragma unroll
    for (int off = 16; off; off >>= 1) sq += __shfl_xor_sync(0xffffffffu, sq, off);
    float inv = rsqrtf(sq * (1.f / 128.f) + 1e-5f);
    float4 gv = *(const float4*)(g + base);
    float o0 = d0 * inv * silu_f(gv.x);
    float o1 = d1 * inv * silu_f(gv.y);
    float o2 = d2 * inv * silu_f(gv.z);
    float o3 = d3 * inv * silu_f(gv.w);
    float4 hv4, lv4;
    split_tf32(o0, hv4.x, lv4.x); split_tf32(o1, hv4.y, lv4.y);
    split_tf32(o2, hv4.z, lv4.z); split_tf32(o3, hv4.w, lv4.w);
    *(float4*)(och + base) = hv4;
    *(float4*)(ocl + base) = lv4;
}

extern "C" void kernel_launch(void* const* d_in, const int* in_sizes, int n_in,
                              void* d_out, int out_size)
{
    const float* x    = (const float*)d_in[0];
    const float* cw   = (const float*)d_in[1];
    const float* Wq   = (const float*)d_in[2];
    const float* Wk   = (const float*)d_in[3];
    const float* Wv   = (const float*)d_in[4];
    const float* Wg   = (const float*)d_in[5];
    const float* rw   = (const float*)d_in[6];
    const float* Wout = (const float*)d_in[7];
    float* out = (float*)d_out;

    float* S = nullptr;
    cudaGetSymbolAddress((void**)&S, g_scratch);
    float* xch   = S;
    float* xcl   = S + 4  * MEG;
    float* Wqk_h = S + 8  * MEG;
    float* Wqk_l = S + 12 * MEG;
    float* Wv_h  = S + 16 * MEG;
    float* Wv_l  = S + 20 * MEG;
    float* Wg_h  = S + 24 * MEG;
    float* Wg_l  = S + 28 * MEG;
    float* Wo_h  = S + 32 * MEG;
    float* Wo_l  = S + 36 * MEG;
    float* qkb   = S + 40 * MEG;
    float* vb    = S + 44 * MEG;
    float* gb    = S + 48 * MEG;
    float* qrh   = S + 52 * MEG;
    float* qrl   = S + 54 * MEG;
    float* krh   = S + 56 * MEG;
    float* krl   = S + 58 * MEG;
    float* v_h   = S + 60 * MEG;
    float* v_l   = S + 64 * MEG;
    float* oa    = S + 68 * MEG;
    float* och   = S + 72 * MEG;
    float* ocl   = S + 76 * MEG;
    int*   slot  = (int*)(S + 80 * MEG);
    float* score = S + 80 * MEG + 32768;
    float* qsc   = S + 80 * MEG + 65536;

    static bool attr_set = false;
    cudaFuncSetAttribute(attn_kernel, cudaFuncAttributeMaxDynamicSharedMemorySize,
                         ATN_SMEM_FLOATS * 4);
    (void)attr_set;

    conv_split_kernel<<<16384, 256>>>(x, cw, xch, xcl);
    qkcat_split_kernel<<<16384, 256>>>(Wq, Wk, Wqk_h, Wqk_l);
    split_kernel<<<16384, 256>>>(Wv, Wv_h, Wv_l);
    split_kernel<<<16384, 256>>>(Wg, Wg_h, Wg_l);
    split_kernel<<<16384, 256>>>(Wout, Wo_h, Wo_l);

    tgemm_ps<<<dim3(16, 16), 256>>>(xch, xcl, Wqk_h, Wqk_l, qkb, 2048, 2048);
    tgemm_ps<<<dim3(16, 16), 256>>>(xch, xcl, Wv_h,  Wv_l,  vb,  2048, 2048);
    tgemm_ps<<<dim3(16, 16), 256>>>(xch, xcl, Wg_h,  Wg_l,  gb,  2048, 2048);

    router_kernel<<<4096, 256>>>(vb, rw, slot, score);
    scan_kernel<<<NH, 256>>>(slot, score, qsc);
    rotary_kernel<<<LSEQ, 256>>>(qkb, qsc, qrh, qrl, krh, krl);
    split_kernel<<<16384, 256>>>(vb, v_h, v_l);

    attn_kernel<<<dim3(32, NH), 256, ATN_SMEM_FLOATS * 4>>>(
        qrh, qrl, krh, krl, v_h, v_l, slot, oa);

    lngate_kernel<<<4096, 256>>>(oa, gb, och, ocl);
    tgemm_ps<<<dim3(16, 16), 256>>>(och, ocl, Wo_h, Wo_l, out, 2048, 2048);
}

// round 7
// speedup vs baseline: 1.3339x; 1.0274x over previous
#include <cuda_runtime.h>
#include <math.h>

#define LSEQ   2048
#define DMODEL 2048
#define NH     16

#define MEG (1u << 20)
__device__ float g_scratch[82u * MEG];

__device__ __forceinline__ float silu_f(float x) { return x / (1.f + expf(-x)); }

__device__ __forceinline__ float f2tf32f(float x) {
    unsigned r;
    asm("cvt.rna.tf32.f32 %0, %1;" : "=r"(r) : "f"(x));
    return __uint_as_float(r);
}
__device__ __forceinline__ void split_tf32(float x, float& hi, float& lo) {
    hi = f2tf32f(x);
    lo = f2tf32f(x - hi);
}

#define MMA_TF32(ACC, AF, BF)                                                   \
    asm volatile(                                                               \
        "mma.sync.aligned.m16n8k8.row.col.f32.tf32.tf32.f32 "                   \
        "{%0,%1,%2,%3},{%4,%5,%6,%7},{%8,%9},{%0,%1,%2,%3};\n"                  \
        : "+f"((ACC)[0]), "+f"((ACC)[1]), "+f"((ACC)[2]), "+f"((ACC)[3])        \
        : "r"((AF)[0]), "r"((AF)[1]), "r"((AF)[2]), "r"((AF)[3]),               \
          "r"((BF)[0]), "r"((BF)[1]))

// ---------------- conv + silu, write split ----------------
__global__ void conv_split_kernel(const float* __restrict__ x, const float* __restrict__ cw,
                                  float* __restrict__ xh, float* __restrict__ xl)
{
    int idx = blockIdx.x * blockDim.x + threadIdx.x;
    int l = idx >> 11;
    int d = idx & (DMODEL - 1);
    float xp = (l > 0) ? x[idx - DMODEL] : 0.f;
    float v  = silu_f(xp * cw[2 * d] + x[idx] * cw[2 * d + 1]);
    float hi, lo; split_tf32(v, hi, lo);
    xh[idx] = hi; xl[idx] = lo;
}

// ---------------- concat Wq|Wk|Wv|Wg (2048 x 6144) and split ----------------
__global__ void wcat_split_kernel(const float* __restrict__ Wq, const float* __restrict__ Wk,
                                  const float* __restrict__ Wv, const float* __restrict__ Wg,
                                  float* __restrict__ wh, float* __restrict__ wl)
{
    int n = blockIdx.x * blockDim.x + threadIdx.x;   // 0..6143
    int k = blockIdx.y;                              // 0..2047
    float w;
    if (n < 1024)      w = Wq[k * 1024 + n];
    else if (n < 2048) w = Wk[k * 1024 + (n - 1024)];
    else if (n < 4096) w = Wv[k * 2048 + (n - 2048)];
    else               w = Wg[k * 2048 + (n - 4096)];
    float hi, lo; split_tf32(w, hi, lo);
    size_t o = (size_t)k * 6144 + n;
    wh[o] = hi; wl[o] = lo;
}

// ---------------- generic split ----------------
__global__ void split_kernel(const float* __restrict__ s, float* __restrict__ hi_o,
                             float* __restrict__ lo_o)
{
    int idx = blockIdx.x * blockDim.x + threadIdx.x;
    float hi, lo; split_tf32(s[idx], hi, lo);
    hi_o[idx] = hi; lo_o[idx] = lo;
}

// ---------------- split v region out of qkvg (stride 6144) ----------------
__global__ void vsplit_kernel(const float* __restrict__ qkvg, float* __restrict__ hi_o,
                              float* __restrict__ lo_o)
{
    int idx = blockIdx.x * blockDim.x + threadIdx.x;   // 0..4M
    int l = idx >> 11, c = idx & 2047;
    float hi, lo; split_tf32(qkvg[(size_t)l * 6144 + 2048 + c], hi, lo);
    hi_o[idx] = hi; lo_o[idx] = lo;
}

// ---------------- split-TF32 GEMM, packed-A smem (LDS.128 fragments) ----------------
// A: M x K row-major (pre-split hi/lo), B: K x N row-major (pre-split). Tile 128x128, k-chunk 8.
// A smem layout: f4[tigk][mblk][perm] where perm = (gidm + 2*tigk) & 7;
//   quad components = { (k,m), (k,m+8), (k+4,m), (k+4,m+8) } -> exactly one mma A-fragment.
#define PB 136
__global__ void __launch_bounds__(256) tgemm_ps(
    const float* __restrict__ Agh, const float* __restrict__ Agl,
    const float* __restrict__ Bgh, const float* __restrict__ Bgl,
    float* __restrict__ C, int N, int K)
{
    __shared__ float Ah[2][1024];
    __shared__ float Al[2][1024];
    __shared__ float Bh[2][8 * PB];
    __shared__ float Bl[2][8 * PB];

    const int tid  = threadIdx.x;
    const int lane = tid & 31;
    const int warp = tid >> 5;
    const int gid  = lane >> 2;
    const int tig  = lane & 3;
    const int wm   = warp >> 2;
    const int wn   = warp & 3;
    const int bx = blockIdx.x, by = blockIdx.y;

    const int mA = tid >> 1;                 // A row 0..127
    const int kA = (tid & 1) << 2;           // A k offset 0/4
    const int kB = tid >> 5;                 // B k 0..7
    const int nB = (tid & 31) << 2;          // B n offset

    // A writer constants
    const int mblk  = mA >> 4;
    const int gidm  = mA & 7;
    const int comp  = ((mA >> 3) & 1) + ((kA >> 2) << 1);

    const size_t aoff = (size_t)(by * 128 + mA) * K + kA;
    const size_t boff = (size_t)kB * N + bx * 128 + nB;

    float acc[4][4][4];
    #pragma unroll
    for (int i = 0; i < 4; i++)
        #pragma unroll
        for (int j = 0; j < 4; j++)
            #pragma unroll
            for (int r = 0; r < 4; r++) acc[i][j][r] = 0.f;

    float4 a4h = *(const float4*)(Agh + aoff);
    float4 a4l = *(const float4*)(Agl + aoff);
    float4 b4h = *(const float4*)(Bgh + boff);
    float4 b4l = *(const float4*)(Bgl + boff);
    {
        float vh[4] = {a4h.x, a4h.y, a4h.z, a4h.w};
        float vl[4] = {a4l.x, a4l.y, a4l.z, a4l.w};
        #pragma unroll
        for (int j = 0; j < 4; j++) {
            int f4 = j * 64 + mblk * 8 + ((gidm + 2 * j) & 7);
            Ah[0][f4 * 4 + comp] = vh[j];
            Al[0][f4 * 4 + comp] = vl[j];
        }
        *(float4*)&Bh[0][kB * PB + nB] = b4h;
        *(float4*)&Bl[0][kB * PB + nB] = b4l;
    }

    int buf = 0;
    for (int k0 = 8; k0 < K; k0 += 8) {
        __syncthreads();
        a4h = *(const float4*)(Agh + aoff + k0);
        a4l = *(const float4*)(Agl + aoff + k0);
        b4h = *(const float4*)(Bgh + boff + (size_t)k0 * N);
        b4l = *(const float4*)(Bgl + boff + (size_t)k0 * N);

        {
            unsigned ah[4][4], al[4][4], bh[4][2], bl[4][2];
            #pragma unroll
            for (int mi = 0; mi < 4; mi++) {
                const int f4 = tig * 64 + (wm * 4 + mi) * 8 + ((gid + 2 * tig) & 7);
                float4 fh = *(const float4*)&Ah[buf][f4 * 4];
                float4 fl = *(const float4*)&Al[buf][f4 * 4];
                ah[mi][0] = __float_as_uint(fh.x); ah[mi][1] = __float_as_uint(fh.y);
                ah[mi][2] = __float_as_uint(fh.z); ah[mi][3] = __float_as_uint(fh.w);
                al[mi][0] = __float_as_uint(fl.x); al[mi][1] = __float_as_uint(fl.y);
                al[mi][2] = __float_as_uint(fl.z); al[mi][3] = __float_as_uint(fl.w);
            }
            #pragma unroll
            for (int ni = 0; ni < 4; ni++) {
                const int off = tig * PB + wn * 32 + ni * 8 + gid;
                bh[ni][0] = __float_as_uint(Bh[buf][off]);
                bh[ni][1] = __float_as_uint(Bh[buf][off + 4 * PB]);
                bl[ni][0] = __float_as_uint(Bl[buf][off]);
                bl[ni][1] = __float_as_uint(Bl[buf][off + 4 * PB]);
            }
            #pragma unroll
            for (int mi = 0; mi < 4; mi++)
                #pragma unroll
                for (int ni = 0; ni < 4; ni++) {
                    MMA_TF32(acc[mi][ni], al[mi], bh[ni]);
                    MMA_TF32(acc[mi][ni], ah[mi], bl[ni]);
                    MMA_TF32(acc[mi][ni], ah[mi], bh[ni]);
                }
        }

        const int nb = buf ^ 1;
        {
            float vh[4] = {a4h.x, a4h.y, a4h.z, a4h.w};
            float vl[4] = {a4l.x, a4l.y, a4l.z, a4l.w};
            #pragma unroll
            for (int j = 0; j < 4; j++) {
                int f4 = j * 64 + mblk * 8 + ((gidm + 2 * j) & 7);
                Ah[nb][f4 * 4 + comp] = vh[j];
                Al[nb][f4 * 4 + comp] = vl[j];
            }
            *(float4*)&Bh[nb][kB * PB + nB] = b4h;
            *(float4*)&Bl[nb][kB * PB + nB] = b4l;
        }
        buf = nb;
    }
    __syncthreads();
    {
        unsigned ah[4][4], al[4][4], bh[4][2], bl[4][2];
        #pragma unroll
        for (int mi = 0; mi < 4; mi++) {
            const int f4 = tig * 64 + (wm * 4 + mi) * 8 + ((gid + 2 * tig) & 7);
            float4 fh = *(const float4*)&Ah[buf][f4 * 4];
            float4 fl = *(const float4*)&Al[buf][f4 * 4];
            ah[mi][0] = __float_as_uint(fh.x); ah[mi][1] = __float_as_uint(fh.y);
            ah[mi][2] = __float_as_uint(fh.z); ah[mi][3] = __float_as_uint(fh.w);
            al[mi][0] = __float_as_uint(fl.x); al[mi][1] = __float_as_uint(fl.y);
            al[mi][2] = __float_as_uint(fl.z); al[mi][3] = __float_as_uint(fl.w);
        }
        #pragma unroll
        for (int ni = 0; ni < 4; ni++) {
            const int off = tig * PB + wn * 32 + ni * 8 + gid;
            bh[ni][0] = __float_as_uint(Bh[buf][off]);
            bh[ni][1] = __float_as_uint(Bh[buf][off + 4 * PB]);
            bl[ni][0] = __float_as_uint(Bl[buf][off]);
            bl[ni][1] = __float_as_uint(Bl[buf][off + 4 * PB]);
        }
        #pragma unroll
        for (int mi = 0; mi < 4; mi++)
            #pragma unroll
            for (int ni = 0; ni < 4; ni++) {
                MMA_TF32(acc[mi][ni], al[mi], bh[ni]);
                MMA_TF32(acc[mi][ni], ah[mi], bl[ni]);
                MMA_TF32(acc[mi][ni], ah[mi], bh[ni]);
            }
    }

    #pragma unroll
    for (int mi = 0; mi < 4; mi++) {
        #pragma unroll
        for (int ni = 0; ni < 4; ni++) {
            int r = by * 128 + wm * 64 + mi * 16 + gid;
            int c = bx * 128 + wn * 32 + ni * 8 + tig * 2;
            *(float2*)(C + (size_t)r * N + c)       = make_float2(acc[mi][ni][0], acc[mi][ni][1]);
            *(float2*)(C + (size_t)(r + 8) * N + c) = make_float2(acc[mi][ni][2], acc[mi][ni][3]);
        }
    }
}

// ---------------- router (v region of qkvg, stride 6144) ----------------
__global__ void router_kernel(const float* __restrict__ qkvg, const float* __restrict__ rw,
                              int* __restrict__ slot, float* __restrict__ score)
{
    int w = (blockIdx.x * blockDim.x + threadIdx.x) >> 5;
    int lane = threadIdx.x & 31;
    int l = w >> 4, h = w & 15;
    const float* vp = qkvg + (size_t)l * 6144 + 2048 + h * 128;
    float4 vv = *(const float4*)(vp + lane * 4);
    const float* rp = rw + h * 256 + lane * 8;
    float4 r0 = *(const float4*)(rp);
    float4 r1 = *(const float4*)(rp + 4);
    float l0 = vv.x * r0.x + vv.y * r0.z + vv.z * r1.x + vv.w * r1.z;
    float l1 = vv.x * r0.y + vv.y * r0.w + vv.z * r1.y + vv.w * r1.w;
    #pragma unroll
    for (int off = 16; off; off >>= 1) {
        l0 += __shfl_xor_sync(0xffffffffu, l0, off);
        l1 += __shfl_xor_sync(0xffffffffu, l1, off);
    }
    if (lane == 0) {
        slot[l * NH + h]  = (l1 > l0) ? 1 : 0;
        score[l * NH + h] = 1.f / (1.f + expf(-fabsf(l0 - l1)));
    }
}

// ---------------- per-head scan ----------------
__global__ void scan_kernel(const int* __restrict__ slot, const float* __restrict__ score,
                            float* __restrict__ qscale)
{
    __shared__ int   sl[LSEQ];
    __shared__ float nm[LSEQ];
    int h = blockIdx.x;
    for (int i = threadIdx.x; i < LSEQ; i += blockDim.x) sl[i] = slot[i * NH + h];
    __syncthreads();
    if (threadIdx.x == 0) {
        int c0 = 0, c1 = 0;
        for (int i = 0; i < LSEQ; i++) {
            int c = sl[i] ? ++c1 : ++c0;
            nm[i] = 1.f / (float)c;
        }
    }
    __syncthreads();
    for (int i = threadIdx.x; i < LSEQ; i += blockDim.x)
        qscale[i * NH + h] = score[i * NH + h] * nm[i] * 0.125f;
}

// ---------------- rotary (q/k regions of qkvg, stride 6144) ----------------
__global__ void rotary_kernel(const float* __restrict__ qkvg, const float* __restrict__ qsc,
                              float* __restrict__ qrh, float* __restrict__ qrl,
                              float* __restrict__ krh, float* __restrict__ krl)
{
    __shared__ float cs[32], sn[32];
    int l = blockIdx.x;
    if (threadIdx.x < 32) {
        float invf = expf(-(float)threadIdx.x * (logf(10000.f) / 32.f));
        float f = (float)l * invf;
        sincosf(f, &sn[threadIdx.x], &cs[threadIdx.x]);
    }
    __syncthreads();
    for (int it = threadIdx.x; it < 2048; it += blockDim.x) {
        int isK = it >> 10;
        int idx = it & 1023;
        int h = idx >> 6, d = idx & 63;
        size_t base = (size_t)l * 6144 + (size_t)isK * 1024 + h * 64;
        float a = qkvg[base + d];
        float b = (d < 32) ? qkvg[base + d + 32] : qkvg[base + d - 32];
        if (!isK) { a = silu_f(a); b = silu_f(b); }
        float val = (d < 32) ? (a * cs[d] - b * sn[d]) : (a * cs[d - 32] + b * sn[d - 32]);
        if (!isK) val *= qsc[l * NH + h];
        float hi, lo; split_tf32(val, hi, lo);
        size_t o = (size_t)l * 1024 + h * 64 + d;
        if (isK) { krh[o] = hi; krl[o] = lo; }
        else     { qrh[o] = hi; qrl[o] = lo; }
    }
}

// ---------------- attention: split-TF32 mma, S^T formulation ----------------
#define ATN_SMEM_FLOATS (2304*2 + 4352*2 + 2304*2)
__global__ void __launch_bounds__(256) attn_kernel(
    const float* __restrict__ qh, const float* __restrict__ ql,
    const float* __restrict__ kh, const float* __restrict__ kl,
    const float* __restrict__ vh, const float* __restrict__ vl,
    const int* __restrict__ slot, float* __restrict__ oa)
{
    extern __shared__ float sm[];
    float* Ksh = sm;
    float* Ksl = sm + 2304;
    float* Vsh = sm + 4608;
    float* Vsl = sm + 8960;
    float* Ssh = sm + 13312;
    float* Ssl = sm + 15616;
    __shared__ int slq[64];
    __shared__ int slk[32];

    const int it   = 31 - blockIdx.x;
    const int h    = blockIdx.y;
    const int tid  = threadIdx.x;
    const int lane = tid & 31, warp = tid >> 5;
    const int gid  = lane >> 2, tig = lane & 3;
    const int row0 = it * 64;
    const int hq = h * 64;
    const int hv = h * 128;
    const int wm1 = warp >> 2, wn1 = warp & 3;
    const int wm2 = warp >> 1, wn2 = warp & 1;

    if (tid < 64) slq[tid] = slot[(row0 + tid) * NH + h];

    unsigned bqh[8][2][2], bql[8][2][2];
    #pragma unroll
    for (int kk = 0; kk < 8; kk++)
        #pragma unroll
        for (int t = 0; t < 2; t++) {
            size_t off = (size_t)(row0 + wn1 * 16 + t * 8 + gid) * 1024 + hq + kk * 8 + tig;
            bqh[kk][t][0] = __float_as_uint(qh[off]);
            bqh[kk][t][1] = __float_as_uint(qh[off + 4]);
            bql[kk][t][0] = __float_as_uint(ql[off]);
            bql[kk][t][1] = __float_as_uint(ql[off + 4]);
        }

    float oacc[8][4];
    #pragma unroll
    for (int ni = 0; ni < 8; ni++)
        #pragma unroll
        for (int r = 0; r < 4; r++) oacc[ni][r] = 0.f;

    const int njt = 2 * it + 2;
    for (int jt = 0; jt < njt; jt++) {
        const int col0 = jt * 32;
        __syncthreads();
        #pragma unroll
        for (int rep = 0; rep < 2; rep++) {
            int e = rep * 256 + tid;
            int j = e >> 4, d4 = (e & 15) << 2;
            size_t go = (size_t)(col0 + j) * 1024 + hq + d4;
            *(float4*)&Ksh[j * 72 + d4] = *(const float4*)(kh + go);
            *(float4*)&Ksl[j * 72 + d4] = *(const float4*)(kl + go);
        }
        #pragma unroll
        for (int rep = 0; rep < 4; rep++) {
            int e = rep * 256 + tid;
            int j = e >> 5, c4 = (e & 31) << 2;
            size_t go = (size_t)(col0 + j) * 2048 + hv + c4;
            *(float4*)&Vsh[j * 136 + c4] = *(const float4*)(vh + go);
            *(float4*)&Vsl[j * 136 + c4] = *(const float4*)(vl + go);
        }
        if (tid < 32) slk[tid] = slot[(col0 + tid) * NH + h];
        __syncthreads();

        float sacc[2][4] = {{0.f,0.f,0.f,0.f},{0.f,0.f,0.f,0.f}};
        #pragma unroll
        for (int kk = 0; kk < 8; kk++) {
            unsigned akh[4], akl[4];
            const int ao = (wm1 * 16 + gid) * 72 + kk * 8 + tig;
            akh[0] = __float_as_uint(Ksh[ao]);
            akh[1] = __float_as_uint(Ksh[ao + 8 * 72]);
            akh[2] = __float_as_uint(Ksh[ao + 4]);
            akh[3] = __float_as_uint(Ksh[ao + 8 * 72 + 4]);
            akl[0] = __float_as_uint(Ksl[ao]);
            akl[1] = __float_as_uint(Ksl[ao + 8 * 72]);
            akl[2] = __float_as_uint(Ksl[ao + 4]);
            akl[3] = __float_as_uint(Ksl[ao + 8 * 72 + 4]);
            #pragma unroll
            for (int t = 0; t < 2; t++) {
                MMA_TF32(sacc[t], akl, bqh[kk][t]);
                MMA_TF32(sacc[t], akh, bql[kk][t]);
                MMA_TF32(sacc[t], akh, bqh[kk][t]);
            }
        }
        {
            int jl0 = wm1 * 16 + gid, jl1 = jl0 + 8;
            int jg0 = col0 + jl0, jg1 = col0 + jl1;
            int sj0 = slk[jl0], sj1 = slk[jl1];
            #pragma unroll
            for (int t = 0; t < 2; t++) {
                int ilc = wn1 * 16 + t * 8 + tig * 2;
                int ig = row0 + ilc;
                int si0 = slq[ilc], si1 = slq[ilc + 1];
                float c0 = (jg0 <= ig     && sj0 == si0) ? sacc[t][0] : 0.f;
                float c1 = (jg0 <= ig + 1 && sj0 == si1) ? sacc[t][1] : 0.f;
                float c2 = (jg1 <= ig     && sj1 == si0) ? sacc[t][2] : 0.f;
                float c3 = (jg1 <= ig + 1 && sj1 == si1) ? sacc[t][3] : 0.f;
                float h0,l0,h1,l1,h2,l2,h3,l3;
                split_tf32(c0,h0,l0); split_tf32(c1,h1,l1);
                split_tf32(c2,h2,l2); split_tf32(c3,h3,l3);
                *(float2*)&Ssh[jl0 * 72 + ilc] = make_float2(h0, h1);
                *(float2*)&Ssl[jl0 * 72 + ilc] = make_float2(l0, l1);
                *(float2*)&Ssh[jl1 * 72 + ilc] = make_float2(h2, h3);
                *(float2*)&Ssl[jl1 * 72 + ilc] = make_float2(l2, l3);
            }
        }
        __syncthreads();

        #pragma unroll
        for (int ks = 0; ks < 4; ks++) {
            unsigned ash[4], asl[4];
            const int ao = (ks * 8 + tig) * 72 + wm2 * 16 + gid;
            ash[0] = __float_as_uint(Ssh[ao]);
            ash[1] = __float_as_uint(Ssh[ao + 8]);
            ash[2] = __float_as_uint(Ssh[ao + 4 * 72]);
            ash[3] = __float_as_uint(Ssh[ao + 4 * 72 + 8]);
            asl[0] = __float_as_uint(Ssl[ao]);
            asl[1] = __float_as_uint(Ssl[ao + 8]);
            asl[2] = __float_as_uint(Ssl[ao + 4 * 72]);
            asl[3] = __float_as_uint(Ssl[ao + 4 * 72 + 8]);
            #pragma unroll
            for (int ni = 0; ni < 8; ni++) {
                unsigned bvh[2], bvl[2];
                const int bo = (ks * 8 + tig) * 136 + wn2 * 64 + ni * 8 + gid;
                bvh[0] = __float_as_uint(Vsh[bo]);
                bvh[1] = __float_as_uint(Vsh[bo + 4 * 136]);
                bvl[0] = __float_as_uint(Vsl[bo]);
                bvl[1] = __float_as_uint(Vsl[bo + 4 * 136]);
                MMA_TF32(oacc[ni], asl, bvh);
                MMA_TF32(oacc[ni], ash, bvl);
                MMA_TF32(oacc[ni], ash, bvh);
            }
        }
    }
    #pragma unroll
    for (int ni = 0; ni < 8; ni++) {
        int i0 = row0 + wm2 * 16 + gid;
        int c = hv + wn2 * 64 + ni * 8 + tig * 2;
        *(float2*)(oa + (size_t)i0 * 2048 + c)       = make_float2(oacc[ni][0], oacc[ni][1]);
        *(float2*)(oa + (size_t)(i0 + 8) * 2048 + c) = make_float2(oacc[ni][2], oacc[ni][3]);
    }
}

// ---------------- layernorm + gate (g region of qkvg), write split ----------------
__global__ void lngate_kernel(const float* __restrict__ oa, const float* __restrict__ qkvg,
                              float* __restrict__ och, float* __restrict__ ocl)
{
    int w = (blockIdx.x * blockDim.x + threadIdx.x) >> 5;
    int lane = threadIdx.x & 31;
    int l = w >> 4, h = w & 15;
    size_t base = (size_t)l * DMODEL + h * 128 + lane * 4;
    size_t gbase = (size_t)l * 6144 + 4096 + h * 128 + lane * 4;
    float4 xv = *(const float4*)(oa + base);
    float s = xv.x + xv.y + xv.z + xv.w;
    #pragma unroll
    for (int off = 16; off; off >>= 1) s += __shfl_xor_sync(0xffffffffu, s, off);
    float mu = s * (1.f / 128.f);
    float d0 = xv.x - mu, d1 = xv.y - mu, d2 = xv.z - mu, d3 = xv.w - mu;
    float sq = d0 * d0 + d1 * d1 + d2 * d2 + d3 * d3;
    #pragma unroll
    for (int off = 16; off; off >>= 1) sq += __shfl_xor_sync(0xffffffffu, sq, off);
    float inv = rsqrtf(sq * (1.f / 128.f) + 1e-5f);
    float4 gv = *(const float4*)(qkvg + gbase);
    float o0 = d0 * inv * silu_f(gv.x);
    float o1 = d1 * inv * silu_f(gv.y);
    float o2 = d2 * inv * silu_f(gv.z);
    float o3 = d3 * inv * silu_f(gv.w);
    float4 hv4, lv4;
    split_tf32(o0, hv4.x, lv4.x); split_tf32(o1, hv4.y, lv4.y);
    split_tf32(o2, hv4.z, lv4.z); split_tf32(o3, hv4.w, lv4.w);
    *(float4*)(och + base) = hv4;
    *(float4*)(ocl + base) = lv4;
}

extern "C" void kernel_launch(void* const* d_in, const int* in_sizes, int n_in,
                              void* d_out, int out_size)
{
    const float* x    = (const float*)d_in[0];
    const float* cw   = (const float*)d_in[1];
    const float* Wq   = (const float*)d_in[2];
    const float* Wk   = (const float*)d_in[3];
    const float* Wv   = (const float*)d_in[4];
    const float* Wg   = (const float*)d_in[5];
    const float* rw   = (const float*)d_in[6];
    const float* Wout = (const float*)d_in[7];
    float* out = (float*)d_out;

    float* S = nullptr;
    cudaGetSymbolAddress((void**)&S, g_scratch);
    float* xch   = S;
    float* xcl   = S + 4  * MEG;
    float* Wc_h  = S + 8  * MEG;   // 12M: Wq|Wk|Wv|Wg hi
    float* Wc_l  = S + 20 * MEG;   // 12M
    float* Wo_h  = S + 32 * MEG;
    float* Wo_l  = S + 36 * MEG;
    float* qkvg  = S + 40 * MEG;   // 12M: L x 6144
    float* qrh   = S + 52 * MEG;
    float* qrl   = S + 54 * MEG;
    float* krh   = S + 56 * MEG;
    float* krl   = S + 58 * MEG;
    float* v_h   = S + 60 * MEG;
    float* v_l   = S + 64 * MEG;
    float* oa    = S + 68 * MEG;
    float* och   = S + 72 * MEG;
    float* ocl   = S + 76 * MEG;
    int*   slot  = (int*)(S + 80 * MEG);
    float* score = S + 80 * MEG + 32768;
    float* qsc   = S + 80 * MEG + 65536;

    cudaFuncSetAttribute(attn_kernel, cudaFuncAttributeMaxDynamicSharedMemorySize,
                         ATN_SMEM_FLOATS * 4);

    conv_split_kernel<<<16384, 256>>>(x, cw, xch, xcl);
    wcat_split_kernel<<<dim3(24, 2048), 256>>>(Wq, Wk, Wv, Wg, Wc_h, Wc_l);
    split_kernel<<<16384, 256>>>(Wout, Wo_h, Wo_l);

    tgemm_ps<<<dim3(48, 16), 256>>>(xch, xcl, Wc_h, Wc_l, qkvg, 6144, 2048);

    router_kernel<<<4096, 256>>>(qkvg, rw, slot, score);
    scan_kernel<<<NH, 256>>>(slot, score, qsc);
    rotary_kernel<<<LSEQ, 256>>>(qkvg, qsc, qrh, qrl, krh, krl);
    vsplit_kernel<<<16384, 256>>>(qkvg, v_h, v_l);

    attn_kernel<<<dim3(32, NH), 256, ATN_SMEM_FLOATS * 4>>>(
        qrh, qrl, krh, krl, v_h, v_l, slot, oa);

    lngate_kernel<<<4096, 256>>>(oa, qkvg, och, ocl);
    tgemm_ps<<<dim3(16, 16), 256>>>(och, ocl, Wo_h, Wo_l, out, 2048, 2048);
}

// round 8
// speedup vs baseline: 1.3368x; 1.0022x over previous
#include <cuda_runtime.h>
#include <math.h>

#define LSEQ   2048
#define DMODEL 2048
#define NH     16

#define MEG (1u << 20)
__device__ float g_scratch[82u * MEG];

__device__ __forceinline__ float silu_f(float x) { return x / (1.f + expf(-x)); }

__device__ __forceinline__ float f2tf32f(float x) {
    unsigned r;
    asm("cvt.rna.tf32.f32 %0, %1;" : "=r"(r) : "f"(x));
    return __uint_as_float(r);
}
__device__ __forceinline__ void split_tf32(float x, float& hi, float& lo) {
    hi = f2tf32f(x);
    lo = f2tf32f(x - hi);
}

#define MMA_TF32(ACC, AF, BF)                                                   \
    asm volatile(                                                               \
        "mma.sync.aligned.m16n8k8.row.col.f32.tf32.tf32.f32 "                   \
        "{%0,%1,%2,%3},{%4,%5,%6,%7},{%8,%9},{%0,%1,%2,%3};\n"                  \
        : "+f"((ACC)[0]), "+f"((ACC)[1]), "+f"((ACC)[2]), "+f"((ACC)[3])        \
        : "r"((AF)[0]), "r"((AF)[1]), "r"((AF)[2]), "r"((AF)[3]),               \
          "r"((BF)[0]), "r"((BF)[1]))

// ---------------- conv + silu, write split ----------------
__global__ void conv_split_kernel(const float* __restrict__ x, const float* __restrict__ cw,
                                  float* __restrict__ xh, float* __restrict__ xl)
{
    int idx = blockIdx.x * blockDim.x + threadIdx.x;
    int l = idx >> 11;
    int d = idx & (DMODEL - 1);
    float xp = (l > 0) ? x[idx - DMODEL] : 0.f;
    float v  = silu_f(xp * cw[2 * d] + x[idx] * cw[2 * d + 1]);
    float hi, lo; split_tf32(v, hi, lo);
    xh[idx] = hi; xl[idx] = lo;
}

// ---------------- concat Wq|Wk|Wv|Wg (2048 x 6144) and split ----------------
__global__ void wcat_split_kernel(const float* __restrict__ Wq, const float* __restrict__ Wk,
                                  const float* __restrict__ Wv, const float* __restrict__ Wg,
                                  float* __restrict__ wh, float* __restrict__ wl)
{
    int n = blockIdx.x * blockDim.x + threadIdx.x;   // 0..6143
    int k = blockIdx.y;                              // 0..2047
    float w;
    if (n < 1024)      w = Wq[k * 1024 + n];
    else if (n < 2048) w = Wk[k * 1024 + (n - 1024)];
    else if (n < 4096) w = Wv[k * 2048 + (n - 2048)];
    else               w = Wg[k * 2048 + (n - 4096)];
    float hi, lo; split_tf32(w, hi, lo);
    size_t o = (size_t)k * 6144 + n;
    wh[o] = hi; wl[o] = lo;
}

// ---------------- generic split ----------------
__global__ void split_kernel(const float* __restrict__ s, float* __restrict__ hi_o,
                             float* __restrict__ lo_o)
{
    int idx = blockIdx.x * blockDim.x + threadIdx.x;
    float hi, lo; split_tf32(s[idx], hi, lo);
    hi_o[idx] = hi; lo_o[idx] = lo;
}

// ---------------- split v region out of qkvg (stride 6144) ----------------
__global__ void vsplit_kernel(const float* __restrict__ qkvg, float* __restrict__ hi_o,
                              float* __restrict__ lo_o)
{
    int idx = blockIdx.x * blockDim.x + threadIdx.x;   // 0..4M
    int l = idx >> 11, c = idx & 2047;
    float hi, lo; split_tf32(qkvg[(size_t)l * 6144 + 2048 + c], hi, lo);
    hi_o[idx] = hi; lo_o[idx] = lo;
}

// ---------------- split-TF32 GEMM, packed-A smem (LDS.128 fragments) ----------------
// A: M x K row-major (pre-split hi/lo), B: K x N row-major (pre-split). Tile 128x128, k-chunk 8.
// A smem layout: f4[tigk][mblk][perm] where perm = (gidm + 2*tigk) & 7;
//   quad components = { (k,m), (k,m+8), (k+4,m), (k+4,m+8) } -> exactly one mma A-fragment.
#define PB 136
__global__ void __launch_bounds__(256) tgemm_ps(
    const float* __restrict__ Agh, const float* __restrict__ Agl,
    const float* __restrict__ Bgh, const float* __restrict__ Bgl,
    float* __restrict__ C, int N, int K)
{
    __shared__ float Ah[2][1024];
    __shared__ float Al[2][1024];
    __shared__ float Bh[2][8 * PB];
    __shared__ float Bl[2][8 * PB];

    const int tid  = threadIdx.x;
    const int lane = tid & 31;
    const int warp = tid >> 5;
    const int gid  = lane >> 2;
    const int tig  = lane & 3;
    const int wm   = warp >> 2;
    const int wn   = warp & 3;
    const int bx = blockIdx.x, by = blockIdx.y;

    const int mA = tid >> 1;                 // A row 0..127
    const int kA = (tid & 1) << 2;           // A k offset 0/4
    const int kB = tid >> 5;                 // B k 0..7
    const int nB = (tid & 31) << 2;          // B n offset

    // A writer constants
    const int mblk  = mA >> 4;
    const int gidm  = mA & 7;
    const int comp  = ((mA >> 3) & 1) + ((kA >> 2) << 1);

    const size_t aoff = (size_t)(by * 128 + mA) * K + kA;
    const size_t boff = (size_t)kB * N + bx * 128 + nB;

    float acc[4][4][4];
    #pragma unroll
    for (int i = 0; i < 4; i++)
        #pragma unroll
        for (int j = 0; j < 4; j++)
            #pragma unroll
            for (int r = 0; r < 4; r++) acc[i][j][r] = 0.f;

    float4 a4h = *(const float4*)(Agh + aoff);
    float4 a4l = *(const float4*)(Agl + aoff);
    float4 b4h = *(const float4*)(Bgh + boff);
    float4 b4l = *(const float4*)(Bgl + boff);
    {
        float vh[4] = {a4h.x, a4h.y, a4h.z, a4h.w};
        float vl[4] = {a4l.x, a4l.y, a4l.z, a4l.w};
        #pragma unroll
        for (int j = 0; j < 4; j++) {
            int f4 = j * 64 + mblk * 8 + ((gidm + 2 * j) & 7);
            Ah[0][f4 * 4 + comp] = vh[j];
            Al[0][f4 * 4 + comp] = vl[j];
        }
        *(float4*)&Bh[0][kB * PB + nB] = b4h;
        *(float4*)&Bl[0][kB * PB + nB] = b4l;
    }

    int buf = 0;
    for (int k0 = 8; k0 < K; k0 += 8) {
        __syncthreads();
        a4h = *(const float4*)(Agh + aoff + k0);
        a4l = *(const float4*)(Agl + aoff + k0);
        b4h = *(const float4*)(Bgh + boff + (size_t)k0 * N);
        b4l = *(const float4*)(Bgl + boff + (size_t)k0 * N);

        {
            unsigned ah[4][4], al[4][4], bh[4][2], bl[4][2];
            #pragma unroll
            for (int mi = 0; mi < 4; mi++) {
                const int f4 = tig * 64 + (wm * 4 + mi) * 8 + ((gid + 2 * tig) & 7);
                float4 fh = *(const float4*)&Ah[buf][f4 * 4];
                float4 fl = *(const float4*)&Al[buf][f4 * 4];
                ah[mi][0] = __float_as_uint(fh.x); ah[mi][1] = __float_as_uint(fh.y);
                ah[mi][2] = __float_as_uint(fh.z); ah[mi][3] = __float_as_uint(fh.w);
                al[mi][0] = __float_as_uint(fl.x); al[mi][1] = __float_as_uint(fl.y);
                al[mi][2] = __float_as_uint(fl.z); al[mi][3] = __float_as_uint(fl.w);
            }
            #pragma unroll
            for (int ni = 0; ni < 4; ni++) {
                const int off = tig * PB + wn * 32 + ni * 8 + gid;
                bh[ni][0] = __float_as_uint(Bh[buf][off]);
                bh[ni][1] = __float_as_uint(Bh[buf][off + 4 * PB]);
                bl[ni][0] = __float_as_uint(Bl[buf][off]);
                bl[ni][1] = __float_as_uint(Bl[buf][off + 4 * PB]);
            }
            #pragma unroll
            for (int mi = 0; mi < 4; mi++)
                #pragma unroll
                for (int ni = 0; ni < 4; ni++) {
                    MMA_TF32(acc[mi][ni], al[mi], bh[ni]);
                    MMA_TF32(acc[mi][ni], ah[mi], bl[ni]);
                    MMA_TF32(acc[mi][ni], ah[mi], bh[ni]);
                }
        }

        const int nb = buf ^ 1;
        {
            float vh[4] = {a4h.x, a4h.y, a4h.z, a4h.w};
            float vl[4] = {a4l.x, a4l.y, a4l.z, a4l.w};
            #pragma unroll
            for (int j = 0; j < 4; j++) {
                int f4 = j * 64 + mblk * 8 + ((gidm + 2 * j) & 7);
                Ah[nb][f4 * 4 + comp] = vh[j];
                Al[nb][f4 * 4 + comp] = vl[j];
            }
            *(float4*)&Bh[nb][kB * PB + nB] = b4h;
            *(float4*)&Bl[nb][kB * PB + nB] = b4l;
        }
        buf = nb;
    }
    __syncthreads();
    {
        unsigned ah[4][4], al[4][4], bh[4][2], bl[4][2];
        #pragma unroll
        for (int mi = 0; mi < 4; mi++) {
            const int f4 = tig * 64 + (wm * 4 + mi) * 8 + ((gid + 2 * tig) & 7);
            float4 fh = *(const float4*)&Ah[buf][f4 * 4];
            float4 fl = *(const float4*)&Al[buf][f4 * 4];
            ah[mi][0] = __float_as_uint(fh.x); ah[mi][1] = __float_as_uint(fh.y);
            ah[mi][2] = __float_as_uint(fh.z); ah[mi][3] = __float_as_uint(fh.w);
            al[mi][0] = __float_as_uint(fl.x); al[mi][1] = __float_as_uint(fl.y);
            al[mi][2] = __float_as_uint(fl.z); al[mi][3] = __float_as_uint(fl.w);
        }
        #pragma unroll
        for (int ni = 0; ni < 4; ni++) {
            const int off = tig * PB + wn * 32 + ni * 8 + gid;
            bh[ni][0] = __float_as_uint(Bh[buf][off]);
            bh[ni][1] = __float_as_uint(Bh[buf][off + 4 * PB]);
            bl[ni][0] = __float_as_uint(Bl[buf][off]);
            bl[ni][1] = __float_as_uint(Bl[buf][off + 4 * PB]);
        }
        #pragma unroll
        for (int mi = 0; mi < 4; mi++)
            #pragma unroll
            for (int ni = 0; ni < 4; ni++) {
                MMA_TF32(acc[mi][ni], al[mi], bh[ni]);
                MMA_TF32(acc[mi][ni], ah[mi], bl[ni]);
                MMA_TF32(acc[mi][ni], ah[mi], bh[ni]);
            }
    }

    #pragma unroll
    for (int mi = 0; mi < 4; mi++) {
        #pragma unroll
        for (int ni = 0; ni < 4; ni++) {
            int r = by * 128 + wm * 64 + mi * 16 + gid;
            int c = bx * 128 + wn * 32 + ni * 8 + tig * 2;
            *(float2*)(C + (size_t)r * N + c)       = make_float2(acc[mi][ni][0], acc[mi][ni][1]);
            *(float2*)(C + (size_t)(r + 8) * N + c) = make_float2(acc[mi][ni][2], acc[mi][ni][3]);
        }
    }
}

// ---------------- router (v region of qkvg, stride 6144) ----------------
__global__ void router_kernel(const float* __restrict__ qkvg, const float* __restrict__ rw,
                              int* __restrict__ slot, float* __restrict__ score)
{
    int w = (blockIdx.x * blockDim.x + threadIdx.x) >> 5;
    int lane = threadIdx.x & 31;
    int l = w >> 4, h = w & 15;
    const float* vp = qkvg + (size_t)l * 6144 + 2048 + h * 128;
    float4 vv = *(const float4*)(vp + lane * 4);
    const float* rp = rw + h * 256 + lane * 8;
    float4 r0 = *(const float4*)(rp);
    float4 r1 = *(const float4*)(rp + 4);
    float l0 = vv.x * r0.x + vv.y * r0.z + vv.z * r1.x + vv.w * r1.z;
    float l1 = vv.x * r0.y + vv.y * r0.w + vv.z * r1.y + vv.w * r1.w;
    #pragma unroll
    for (int off = 16; off; off >>= 1) {
        l0 += __shfl_xor_sync(0xffffffffu, l0, off);
        l1 += __shfl_xor_sync(0xffffffffu, l1, off);
    }
    if (lane == 0) {
        slot[l * NH + h]  = (l1 > l0) ? 1 : 0;
        score[l * NH + h] = 1.f / (1.f + expf(-fabsf(l0 - l1)));
    }
}

// ---------------- per-head scan ----------------
__global__ void scan_kernel(const int* __restrict__ slot, const float* __restrict__ score,
                            float* __restrict__ qscale)
{
    __shared__ int   sl[LSEQ];
    __shared__ float nm[LSEQ];
    int h = blockIdx.x;
    for (int i = threadIdx.x; i < LSEQ; i += blockDim.x) sl[i] = slot[i * NH + h];
    __syncthreads();
    if (threadIdx.x == 0) {
        int c0 = 0, c1 = 0;
        for (int i = 0; i < LSEQ; i++) {
            int c = sl[i] ? ++c1 : ++c0;
            nm[i] = 1.f / (float)c;
        }
    }
    __syncthreads();
    for (int i = threadIdx.x; i < LSEQ; i += blockDim.x)
        qscale[i * NH + h] = score[i * NH + h] * nm[i] * 0.125f;
}

// ---------------- rotary (q/k regions of qkvg, stride 6144) ----------------
__global__ void rotary_kernel(const float* __restrict__ qkvg, const float* __restrict__ qsc,
                              float* __restrict__ qrh, float* __restrict__ qrl,
                              float* __restrict__ krh, float* __restrict__ krl)
{
    __shared__ float cs[32], sn[32];
    int l = blockIdx.x;
    if (threadIdx.x < 32) {
        float invf = expf(-(float)threadIdx.x * (logf(10000.f) / 32.f));
        float f = (float)l * invf;
        sincosf(f, &sn[threadIdx.x], &cs[threadIdx.x]);
    }
    __syncthreads();
    for (int it = threadIdx.x; it < 2048; it += blockDim.x) {
        int isK = it >> 10;
        int idx = it & 1023;
        int h = idx >> 6, d = idx & 63;
        size_t base = (size_t)l * 6144 + (size_t)isK * 1024 + h * 64;
        float a = qkvg[base + d];
        float b = (d < 32) ? qkvg[base + d + 32] : qkvg[base + d - 32];
        if (!isK) { a = silu_f(a); b = silu_f(b); }
        float val = (d < 32) ? (a * cs[d] - b * sn[d]) : (a * cs[d - 32] + b * sn[d - 32]);
        if (!isK) val *= qsc[l * NH + h];
        float hi, lo; split_tf32(val, hi, lo);
        size_t o = (size_t)l * 1024 + h * 64 + d;
        if (isK) { krh[o] = hi; krl[o] = lo; }
        else     { qrh[o] = hi; qrl[o] = lo; }
    }
}

// ---------------- attention: split-TF32 mma, S^T formulation ----------------
#define ATN_SMEM_FLOATS (2304*2 + 4352*2 + 2304*2)
__global__ void __launch_bounds__(256) attn_kernel(
    const float* __restrict__ qh, const float* __restrict__ ql,
    const float* __restrict__ kh, const float* __restrict__ kl,
    const float* __restrict__ vh, const float* __restrict__ vl,
    const int* __restrict__ slot, float* __restrict__ oa)
{
    extern __shared__ float sm[];
    float* Ksh = sm;
    float* Ksl = sm + 2304;
    float* Vsh = sm + 4608;
    float* Vsl = sm + 8960;
    float* Ssh = sm + 13312;
    float* Ssl = sm + 15616;
    __shared__ int slq[64];
    __shared__ int slk[32];

    const int it   = 31 - blockIdx.x;
    const int h    = blockIdx.y;
    const int tid  = threadIdx.x;
    const int lane = tid & 31, warp = tid >> 5;
    const int gid  = lane >> 2, tig = lane & 3;
    const int row0 = it * 64;
    const int hq = h * 64;
    const int hv = h * 128;
    const int wm1 = warp >> 2, wn1 = warp & 3;
    const int wm2 = warp >> 1, wn2 = warp & 1;

    if (tid < 64) slq[tid] = slot[(row0 + tid) * NH + h];

    unsigned bqh[8][2][2], bql[8][2][2];
    #pragma unroll
    for (int kk = 0; kk < 8; kk++)
        #pragma unroll
        for (int t = 0; t < 2; t++) {
            size_t off = (size_t)(row0 + wn1 * 16 + t * 8 + gid) * 1024 + hq + kk * 8 + tig;
            bqh[kk][t][0] = __float_as_uint(qh[off]);
            bqh[kk][t][1] = __float_as_uint(qh[off + 4]);
            bql[kk][t][0] = __float_as_uint(ql[off]);
            bql[kk][t][1] = __float_as_uint(ql[off + 4]);
        }

    float oacc[8][4];
    #pragma unroll
    for (int ni = 0; ni < 8; ni++)
        #pragma unroll
        for (int r = 0; r < 4; r++) oacc[ni][r] = 0.f;

    const int njt = 2 * it + 2;
    for (int jt = 0; jt < njt; jt++) {
        const int col0 = jt * 32;
        __syncthreads();
        #pragma unroll
        for (int rep = 0; rep < 2; rep++) {
            int e = rep * 256 + tid;
            int j = e >> 4, d4 = (e & 15) << 2;
            size_t go = (size_t)(col0 + j) * 1024 + hq + d4;
            *(float4*)&Ksh[j * 72 + d4] = *(const float4*)(kh + go);
            *(float4*)&Ksl[j * 72 + d4] = *(const float4*)(kl + go);
        }
        #pragma unroll
        for (int rep = 0; rep < 4; rep++) {
            int e = rep * 256 + tid;
            int j = e >> 5, c4 = (e & 31) << 2;
            size_t go = (size_t)(col0 + j) * 2048 + hv + c4;
            *(float4*)&Vsh[j * 136 + c4] = *(const float4*)(vh + go);
            *(float4*)&Vsl[j * 136 + c4] = *(const float4*)(vl + go);
        }
        if (tid < 32) slk[tid] = slot[(col0 + tid) * NH + h];
        __syncthreads();

        float sacc[2][4] = {{0.f,0.f,0.f,0.f},{0.f,0.f,0.f,0.f}};
        #pragma unroll
        for (int kk = 0; kk < 8; kk++) {
            unsigned akh[4], akl[4];
            const int ao = (wm1 * 16 + gid) * 72 + kk * 8 + tig;
            akh[0] = __float_as_uint(Ksh[ao]);
            akh[1] = __float_as_uint(Ksh[ao + 8 * 72]);
            akh[2] = __float_as_uint(Ksh[ao + 4]);
            akh[3] = __float_as_uint(Ksh[ao + 8 * 72 + 4]);
            akl[0] = __float_as_uint(Ksl[ao]);
            akl[1] = __float_as_uint(Ksl[ao + 8 * 72]);
            akl[2] = __float_as_uint(Ksl[ao + 4]);
            akl[3] = __float_as_uint(Ksl[ao + 8 * 72 + 4]);
            #pragma unroll
            for (int t = 0; t < 2; t++) {
                MMA_TF32(sacc[t], akl, bqh[kk][t]);
                MMA_TF32(sacc[t], akh, bql[kk][t]);
                MMA_TF32(sacc[t], akh, bqh[kk][t]);
            }
        }
        {
            int jl0 = wm1 * 16 + gid, jl1 = jl0 + 8;
            int jg0 = col0 + jl0, jg1 = col0 + jl1;
            int sj0 = slk[jl0], sj1 = slk[jl1];
            #pragma unroll
            for (int t = 0; t < 2; t++) {
                int ilc = wn1 * 16 + t * 8 + tig * 2;
                int ig = row0 + ilc;
                int si0 = slq[ilc], si1 = slq[ilc + 1];
                float c0 = (jg0 <= ig     && sj0 == si0) ? sacc[t][0] : 0.f;
                float c1 = (jg0 <= ig + 1 && sj0 == si1) ? sacc[t][1] : 0.f;
                float c2 = (jg1 <= ig     && sj1 == si0) ? sacc[t][2] : 0.f;
                float c3 = (jg1 <= ig + 1 && sj1 == si1) ? sacc[t][3] : 0.f;
                float h0,l0,h1,l1,h2,l2,h3,l3;
                split_tf32(c0,h0,l0); split_tf32(c1,h1,l1);
                split_tf32(c2,h2,l2); split_tf32(c3,h3,l3);
                *(float2*)&Ssh[jl0 * 72 + ilc] = make_float2(h0, h1);
                *(float2*)&Ssl[jl0 * 72 + ilc] = make_float2(l0, l1);
                *(float2*)&Ssh[jl1 * 72 + ilc] = make_float2(h2, h3);
                *(float2*)&Ssl[jl1 * 72 + ilc] = make_float2(l2, l3);
            }
        }
        __syncthreads();

        #pragma unroll
        for (int ks = 0; ks < 4; ks++) {
            unsigned ash[4], asl[4];
            const int ao = (ks * 8 + tig) * 72 + wm2 * 16 + gid;
            ash[0] = __float_as_uint(Ssh[ao]);
            ash[1] = __float_as_uint(Ssh[ao + 8]);
            ash[2] = __float_as_uint(Ssh[ao + 4 * 72]);
            ash[3] = __float_as_uint(Ssh[ao + 4 * 72 + 8]);
            asl[0] = __float_as_uint(Ssl[ao]);
            asl[1] = __float_as_uint(Ssl[ao + 8]);
            asl[2] = __float_as_uint(Ssl[ao + 4 * 72]);
            asl[3] = __float_as_uint(Ssl[ao + 4 * 72 + 8]);
            #pragma unroll
            for (int ni = 0; ni < 8; ni++) {
                unsigned bvh[2], bvl[2];
                const int bo = (ks * 8 + tig) * 136 + wn2 * 64 + ni * 8 + gid;
                bvh[0] = __float_as_uint(Vsh[bo]);
                bvh[1] = __float_as_uint(Vsh[bo + 4 * 136]);
                bvl[0] = __float_as_uint(Vsl[bo]);
                bvl[1] = __float_as_uint(Vsl[bo + 4 * 136]);
                MMA_TF32(oacc[ni], asl, bvh);
                MMA_TF32(oacc[ni], ash, bvl);
                MMA_TF32(oacc[ni], ash, bvh);
            }
        }
    }
    #pragma unroll
    for (int ni = 0; ni < 8; ni++) {
        int i0 = row0 + wm2 * 16 + gid;
        int c = hv + wn2 * 64 + ni * 8 + tig * 2;
        *(float2*)(oa + (size_t)i0 * 2048 + c)       = make_float2(oacc[ni][0], oacc[ni][1]);
        *(float2*)(oa + (size_t)(i0 + 8) * 2048 + c) = make_float2(oacc[ni][2], oacc[ni][3]);
    }
}

// ---------------- layernorm + gate (g region of qkvg), write split ----------------
__global__ void lngate_kernel(const float* __restrict__ oa, const float* __restrict__ qkvg,
                              float* __restrict__ och, float* __restrict__ ocl)
{
    int w = (blockIdx.x * blockDim.x + threadIdx.x) >> 5;
    int lane = threadIdx.x & 31;
    int l = w >> 4, h = w & 15;
    size_t base = (size_t)l * DMODEL + h * 128 + lane * 4;
    size_t gbase = (size_t)l * 6144 + 4096 + h * 128 + lane * 4;
    float4 xv = *(const float4*)(oa + base);
    float s = xv.x + xv.y + xv.z + xv.w;
    #pragma unroll
    for (int off = 16; off; off >>= 1) s += __shfl_xor_sync(0xffffffffu, s, off);
    float mu = s * (1.f / 128.f);
    float d0 = xv.x - mu, d1 = xv.y - mu, d2 = xv.z - mu, d3 = xv.w - mu;
    float sq = d0 * d0 + d1 * d1 + d2 * d2 + d3 * d3;
    #pragma unroll
    for (int off = 16; off; off >>= 1) sq += __shfl_xor_sync(0xffffffffu, sq, off);
    float inv = rsqrtf(sq * (1.f / 128.f) + 1e-5f);
    float4 gv = *(const float4*)(qkvg + gbase);
    float o0 = d0 * inv * silu_f(gv.x);
    float o1 = d1 * inv * silu_f(gv.y);
    float o2 = d2 * inv * silu_f(gv.z);
    float o3 = d3 * inv * silu_f(gv.w);
    float4 hv4, lv4;
    split_tf32(o0, hv4.x, lv4.x); split_tf32(o1, hv4.y, lv4.y);
    split_tf32(o2, hv4.z, lv4.z); split_tf32(o3, hv4.w, lv4.w);
    *(float4*)(och + base) = hv4;
    *(float4*)(ocl + base) = lv4;
}

extern "C" void kernel_launch(void* const* d_in, const int* in_sizes, int n_in,
                              void* d_out, int out_size)
{
    const float* x    = (const float*)d_in[0];
    const float* cw   = (const float*)d_in[1];
    const float* Wq   = (const float*)d_in[2];
    const float* Wk   = (const float*)d_in[3];
    const float* Wv   = (const float*)d_in[4];
    const float* Wg   = (const float*)d_in[5];
    const float* rw   = (const float*)d_in[6];
    const float* Wout = (const float*)d_in[7];
    float* out = (float*)d_out;

    float* S = nullptr;
    cudaGetSymbolAddress((void**)&S, g_scratch);
    float* xch   = S;
    float* xcl   = S + 4  * MEG;
    float* Wc_h  = S + 8  * MEG;   // 12M: Wq|Wk|Wv|Wg hi
    float* Wc_l  = S + 20 * MEG;   // 12M
    float* Wo_h  = S + 32 * MEG;
    float* Wo_l  = S + 36 * MEG;
    float* qkvg  = S + 40 * MEG;   // 12M: L x 6144
    float* qrh   = S + 52 * MEG;
    float* qrl   = S + 54 * MEG;
    float* krh   = S + 56 * MEG;
    float* krl   = S + 58 * MEG;
    float* v_h   = S + 60 * MEG;
    float* v_l   = S + 64 * MEG;
    float* oa    = S + 68 * MEG;
    float* och   = S + 72 * MEG;
    float* ocl   = S + 76 * MEG;
    int*   slot  = (int*)(S + 80 * MEG);
    float* score = S + 80 * MEG + 32768;
    float* qsc   = S + 80 * MEG + 65536;

    cudaFuncSetAttribute(attn_kernel, cudaFuncAttributeMaxDynamicSharedMemorySize,
                         ATN_SMEM_FLOATS * 4);

    conv_split_kernel<<<16384, 256>>>(x, cw, xch, xcl);
    wcat_split_kernel<<<dim3(24, 2048), 256>>>(Wq, Wk, Wv, Wg, Wc_h, Wc_l);
    split_kernel<<<16384, 256>>>(Wout, Wo_h, Wo_l);

    tgemm_ps<<<dim3(48, 16), 256>>>(xch, xcl, Wc_h, Wc_l, qkvg, 6144, 2048);

    router_kernel<<<4096, 256>>>(qkvg, rw, slot, score);
    scan_kernel<<<NH, 256>>>(slot, score, qsc);
    rotary_kernel<<<LSEQ, 256>>>(qkvg, qsc, qrh, qrl, krh, krl);
    vsplit_kernel<<<16384, 256>>>(qkvg, v_h, v_l);

    attn_kernel<<<dim3(32, NH), 256, ATN_SMEM_FLOATS * 4>>>(
        qrh, qrl, krh, krl, v_h, v_l, slot, oa);

    lngate_kernel<<<4096, 256>>>(oa, qkvg, och, ocl);
    tgemm_ps<<<dim3(16, 16), 256>>>(och, ocl, Wo_h, Wo_l, out, 2048, 2048);
}